// round 8
// baseline (speedup 1.0000x reference)
#include <cuda_runtime.h>

#define YS 256
#define XS 16
#define TS 2048
#define TM1 2047

// Output packing (float32), reference return order:
// alpha (T*Y) | beta (T*Y) | p (1) | gamma (T*Y) | xi ((T-1)*Y*Y) | path (T)
#define OFF_ALPHA 0
#define OFF_BETA  (TS * YS)
#define OFF_P     (2 * TS * YS)
#define OFF_GAMMA (2 * TS * YS + 1)
#define OFF_XI    ((size_t)(3 * TS * YS + 1))
#define OFF_PATH  (OFF_XI + (size_t)TM1 * YS * YS)

#define MSTRIDE 36   // padded row stride (floats): lane*144B distinct 16B banks
#define NSLOT 3      // ring depth 3 (depth 2 races: producer 2 steps ahead)

// Scratch (static device memory — no allocations)
__device__ float g_bx[TS * YS];          // bx[t][j] = b[j, x[t]]
__device__ unsigned char g_bp[TM1 * YS]; // Viterbi backpointers (values 0..255)
__device__ float g_p;

// FTZ multiply — matches reference runtime's flush-to-zero f32 (verified R6).
__device__ __forceinline__ float fmul_ftz(float a, float b) {
    float r;
    asm("mul.rn.ftz.f32 %0, %1, %2;" : "=f"(r) : "f"(a), "f"(b));
    return r;
}

__device__ __forceinline__ unsigned int smem_u32(const void* p) {
    unsigned int a;
    asm("{ .reg .u64 t; cvta.to.shared.u64 t, %1; cvt.u32.u64 %0, t; }"
        : "=r"(a) : "l"(p));
    return a;
}

__device__ __forceinline__ unsigned int ctarank() {
    unsigned int r;
    asm("mov.u32 %0, %%cluster_ctarank;" : "=r"(r));
    return r;
}

// Producer: remote v4 store + release-arrive on the remote slot mbarrier.
// Same-thread program order + .release.cluster orders the store before the
// arrive for any consumer that acquires on that mbarrier.
__device__ __forceinline__ void push_arrive(unsigned int bufaddr, unsigned int mbaraddr,
                                            unsigned int rank, float4 v) {
    asm volatile(
        "{ .reg .b32 ra, rb;\n\t"
        "mapa.shared::cluster.u32 ra, %0, %2;\n\t"
        "st.shared::cluster.v4.f32 [ra], {%3,%4,%5,%6};\n\t"
        "mapa.shared::cluster.u32 rb, %1, %2;\n\t"
        "mbarrier.arrive.release.cluster.shared::cluster.b64 _, [rb];\n\t"
        "}"
        :: "r"(bufaddr), "r"(mbaraddr), "r"(rank),
           "f"(v.x), "f"(v.y), "f"(v.z), "f"(v.w) : "memory");
}

// Consumer: parity wait with cluster-scope acquire (DSMEM-written data).
__device__ __forceinline__ void mbar_wait(unsigned int addr, unsigned int parity) {
    asm volatile(
        "{ .reg .pred P;\n\t"
        "WL%=:\n\t"
        "mbarrier.try_wait.parity.acquire.cluster.shared::cta.b64 P, [%0], %1, 0x989680;\n\t"
        "@P bra WD%=;\n\t"
        "bra WL%=;\n\t"
        "WD%=: }"
        :: "r"(addr), "r"(parity) : "memory");
}

#define CLUSTER_ARRIVE() asm volatile("barrier.cluster.arrive.aligned;" ::: "memory")
#define CLUSTER_WAIT()   asm volatile("barrier.cluster.wait.aligned;" ::: "memory")

// ---------------------------------------------------------------- prep
__global__ void prep_bx_kernel(const int* __restrict__ x,
                               const float* __restrict__ b) {
    int t = blockIdx.x;
    int j = threadIdx.x;
    g_bx[t * YS + j] = b[j * XS + x[t]];
}

// ---------------------------------------------------------------- recurrences
// grid = 24 CTAs = 3 clusters of 8. Cluster r: 0=alpha, 1=beta, 2=Viterbi.
// CTA g owns output columns [g*32, g*32+32); matrix slice in SMEM. Per step:
// compute 32 outputs from the local copy of the full 256-vector, push quads to
// all 8 CTAs' slot-(s+1)%3 buffer via DSMEM + release-arrive; consumers
// acquire-wait the slot mbarrier (count 64) at the top of the next step.
__global__ void __cluster_dims__(8, 1, 1)
recur_cluster_kernel(const float* __restrict__ A,
                     const float* __restrict__ pi,
                     float* __restrict__ out) {
    __shared__ __align__(16) float Ms[YS * MSTRIDE];       // 36 KB slice
    __shared__ __align__(16) float s_buf[NSLOT][YS];       // slot ring
    __shared__ __align__(8) unsigned long long s_mbar[NSLOT];
    __shared__ unsigned int s_redu[8];
    __shared__ float s_redf[8];
    __shared__ int s_dead;
    __shared__ int s_last;

    const int tid  = threadIdx.x;
    const int w    = tid >> 5;
    const int lane = tid & 31;
    const int c0   = w * 4;                 // local column quad
    const unsigned int g = ctarank();
    const int r    = blockIdx.x >> 3;       // recursion id
    const int colg = (int)g * 32 + c0;      // global column base of this warp

    const unsigned int bufu  = smem_u32(&s_buf[0][0]);
    const unsigned int mbaru = smem_u32(&s_mbar[0]);

    // ---- init mbarriers (count 64 = 8 CTAs x 8 warps) ----
    if (tid == 0) {
#pragma unroll
        for (int sl = 0; sl < NSLOT; ++sl)
            asm volatile("mbarrier.init.shared.b64 [%0], 64;"
                         :: "r"(mbaru + sl * 8) : "memory");
        s_dead = 0;
        s_last = 0;
    }

    // ---- load matrix slice into SMEM ----
    if (r != 1) {
        // alpha/viterbi: Ms[k][c] = A[k][g*32+c]   (out_c = sum_k v[k]*A[k][c])
        for (int idx = tid; idx < YS * 32; idx += YS) {
            int k = idx >> 5, c = idx & 31;
            Ms[k * MSTRIDE + c] = A[k * YS + (int)g * 32 + c];
        }
    } else {
        // beta: Ms[k][c] = A[g*32+c][k]            (out_c = sum_k w[k]*A[c][k])
        for (int cc = 0; cc < 32; ++cc)
            Ms[tid * MSTRIDE + cc] = A[((int)g * 32 + cc) * YS + tid];
    }

    // ---- init v0 (slot 0, local) and boundary rows ----
    if (r == 0) {
        float a0 = g_bx[tid] * pi[tid];
        s_buf[0][tid] = a0;
        if (g == 0) out[OFF_ALPHA + tid] = a0;
    } else if (r == 1) {
        s_buf[0][tid] = g_bx[(TS - 1) * YS + tid];   // w[T-1] = bx[T-1] * 1
        if (g == 0) out[OFF_BETA + (TS - 1) * YS + tid] = 1.0f;
    } else {
        s_buf[0][tid] = g_bx[tid] * pi[tid];
    }
    __syncthreads();
    CLUSTER_ARRIVE();   // all mbars initialized before any remote arrive
    CLUSTER_WAIT();

    const int S = TS - 1;  // 2047 steps
    int tz = -1;
    unsigned int ph0 = 0, ph1 = 0, ph2 = 0;  // per-slot parity

    // bx prefetch for step 0
    int t0 = (r == 1) ? (TS - 2) : 1;
    float4 bxv = __ldg((const float4*)&g_bx[t0 * YS + colg]);

    for (int s = 0; s < S; ++s) {
        const int slot = s % NSLOT;
        const int slot2 = (s + 1) % NSLOT;
        const int t = (r == 1) ? (TS - 2 - s) : (s + 1);

        // wait for this step's input (step 0's input is local)
        if (s > 0) {
            unsigned int p = (slot == 0) ? ph0 : (slot == 1 ? ph1 : ph2);
            mbar_wait(mbaru + slot * 8, p);
            if (slot == 0) ph0 ^= 1u; else if (slot == 1) ph1 ^= 1u; else ph2 ^= 1u;
        }

        // gather v into registers (k = kk*32 + lane)
        float vreg[8];
        unsigned int orv = 0u;
#pragma unroll
        for (int kk = 0; kk < 8; ++kk) {
            vreg[kk] = s_buf[slot][kk * 32 + lane];
            orv |= __float_as_uint(vreg[kk]);
        }

        if (r == 2) {
            // all-zero detection (identical buffers in every CTA -> uniform)
            unsigned int o = __reduce_or_sync(0xffffffffu, orv);
            if (lane == 0) s_redu[w] = o;
            __syncthreads();
            if (tid == 0) {
                unsigned int oo = 0u;
                for (int i = 0; i < 8; ++i) oo |= s_redu[i];
                if (oo == 0u) s_dead = 1;
            }
            __syncthreads();
            if (s_dead) { tz = s; break; }
        }

        const unsigned int nbuf = bufu + (unsigned int)(slot2 * YS + colg) * 4u;
        const unsigned int nmb  = mbaru + slot2 * 8;

        if (r != 2) {
            float4 acc = make_float4(0.f, 0.f, 0.f, 0.f);
#pragma unroll
            for (int kk = 0; kk < 8; ++kk) {
                float vv = vreg[kk];
                float4 m = *(const float4*)&Ms[(kk * 32 + lane) * MSTRIDE + c0];
                acc.x = fmaf(vv, m.x, acc.x);
                acc.y = fmaf(vv, m.y, acc.y);
                acc.z = fmaf(vv, m.z, acc.z);
                acc.w = fmaf(vv, m.w, acc.w);
            }
#pragma unroll
            for (int off = 16; off > 0; off >>= 1) {
                acc.x += __shfl_xor_sync(0xffffffffu, acc.x, off);
                acc.y += __shfl_xor_sync(0xffffffffu, acc.y, off);
                acc.z += __shfl_xor_sync(0xffffffffu, acc.z, off);
                acc.w += __shfl_xor_sync(0xffffffffu, acc.w, off);
            }
            // pushed value includes the bx factor for the NEXT step
            float4 push;
            push.x = acc.x * bxv.x;
            push.y = acc.y * bxv.y;
            push.z = acc.z * bxv.z;
            push.w = acc.w * bxv.w;
            if (lane < 8)
                push_arrive(nbuf, nmb, lane, push);
            if (lane == 8) {
                if (r == 0)
                    *(float4*)&out[OFF_ALPHA + t * YS + colg] = push;  // alpha = sum*bx
                else
                    *(float4*)&out[OFF_BETA + t * YS + colg] = acc;   // beta raw
            }
        } else {
            // Viterbi: max/argmax over k, FTZ muls, first-max tie semantics
            unsigned int bu[4] = {0u, 0u, 0u, 0u};
            int bi[4] = {lane, lane, lane, lane};
#pragma unroll
            for (int kk = 0; kk < 8; ++kk) {
                int k = kk * 32 + lane;
                float vv = vreg[kk];
                float4 m = *(const float4*)&Ms[k * MSTRIDE + c0];
                unsigned int s0 = __float_as_uint(fmul_ftz(vv, m.x));
                unsigned int s1 = __float_as_uint(fmul_ftz(vv, m.y));
                unsigned int s2 = __float_as_uint(fmul_ftz(vv, m.z));
                unsigned int s3 = __float_as_uint(fmul_ftz(vv, m.w));
                if (s0 > bu[0]) { bu[0] = s0; bi[0] = k; }
                if (s1 > bu[1]) { bu[1] = s1; bi[1] = k; }
                if (s2 > bu[2]) { bu[2] = s2; bi[2] = k; }
                if (s3 > bu[3]) { bu[3] = s3; bi[3] = k; }
            }
#pragma unroll
            for (int off = 16; off > 0; off >>= 1) {
#pragma unroll
                for (int j = 0; j < 4; ++j) {
                    unsigned int ou = __shfl_xor_sync(0xffffffffu, bu[j], off);
                    int oi = __shfl_xor_sync(0xffffffffu, bi[j], off);
                    if (ou > bu[j] || (ou == bu[j] && oi < bi[j])) {
                        bu[j] = ou; bi[j] = oi;
                    }
                }
            }
            float4 push;
            push.x = fmul_ftz(bxv.x, __uint_as_float(bu[0]));
            push.y = fmul_ftz(bxv.y, __uint_as_float(bu[1]));
            push.z = fmul_ftz(bxv.z, __uint_as_float(bu[2]));
            push.w = fmul_ftz(bxv.w, __uint_as_float(bu[3]));
            if (lane < 8)
                push_arrive(nbuf, nmb, lane, push);
            if (lane == 8) {
                unsigned int pack = (unsigned int)bi[0] | ((unsigned int)bi[1] << 8)
                                  | ((unsigned int)bi[2] << 16) | ((unsigned int)bi[3] << 24);
                *(unsigned int*)(g_bp + (size_t)(t - 1) * YS + colg) = pack;
            }
        }

        if (s + 1 < S) {
            int tn = (r == 1) ? (TS - 2 - (s + 1)) : (s + 2);
            bxv = __ldg((const float4*)&g_bx[tn * YS + colg]);
        }
    }

    // ---- epilogues ----
    if (r == 0) {
        // p = sum(alpha[T-1]): final vector pushed into slot S%NSLOT
        if (g == 0) {
            const int fslot = S % NSLOT;
            unsigned int p = (fslot == 0) ? ph0 : (fslot == 1 ? ph1 : ph2);
            mbar_wait(mbaru + fslot * 8, p);
            float v = s_buf[fslot][tid];
#pragma unroll
            for (int off = 16; off > 0; off >>= 1)
                v += __shfl_xor_sync(0xffffffffu, v, off);
            if (lane == 0) s_redf[w] = v;
            __syncthreads();
            if (tid == 0) {
                float pp = 0.f;
                for (int i = 0; i < 8; ++i) pp += s_redf[i];
                out[OFF_P] = pp;
                g_p = pp;
            }
        }
    } else if (r == 2) {
        // zero-fill bp rows [tz, TM1) across the cluster (V dead from tz on)
        if (tz >= 0) {
            unsigned int* bp32 = (unsigned int*)(g_bp + (size_t)tz * YS);
            int n32 = (TM1 - tz) * (YS / 4);
            for (int i = (int)g * YS + tid; i < n32; i += 8 * YS) bp32[i] = 0u;
        }
        CLUSTER_ARRIVE();
        CLUSTER_WAIT();
        if (g == 0) {
            if (tz >= 0) {
                for (int k = tz + tid; k < TS - 1; k += YS)
                    out[OFF_PATH + k] = 0.0f;
                // s_last already 0
            } else if (tid == 0) {
                const int fslot = S % NSLOT;
                unsigned int p = (fslot == 0) ? ph0 : (fslot == 1 ? ph1 : ph2);
                mbar_wait(mbaru + fslot * 8, p);
                unsigned int m = __float_as_uint(s_buf[fslot][0]);
                int idx = 0;
                for (int i = 1; i < YS; ++i) {
                    unsigned int vi = __float_as_uint(s_buf[fslot][i]);
                    if (vi > m) { m = vi; idx = i; }
                }
                s_last = idx;
            }
            __syncthreads();
            if (tid == 0) {
                int last = s_last;
                out[OFF_PATH + TS - 1] = (float)last;
                int st = last;
                int tstart = (tz >= 0) ? (tz - 1) : (TS - 2);
                for (int t = tstart; t >= 0; --t) {
                    st = (int)g_bp[(size_t)t * YS + st];
                    out[OFF_PATH + t] = (float)st;
                }
            }
        }
    }

    // collective exit: no CTA leaves while in-flight DSMEM ops may target it
    CLUSTER_ARRIVE();
    CLUSTER_WAIT();
}

// ---------------------------------------------------------------- gamma
__global__ void gamma_kernel(float* __restrict__ out) {
    int idx = blockIdx.x * YS + threadIdx.x;
    float p = g_p;
    out[OFF_GAMMA + idx] = out[OFF_ALPHA + idx] * out[OFF_BETA + idx] / p;
}

// ---------------------------------------------------------------- xi
// Block handles XB consecutive t: A row read once from L2, 4 stores amortize
// it (L2 A-traffic /4). OFF_XI is odd -> region 4B-aligned -> scalar STG.32.
#define XB 4
__global__ void xi_kernel(const float* __restrict__ A, float* __restrict__ out) {
    __shared__ __align__(16) float s_a[XB][YS];
    __shared__ __align__(16) float s_w[XB][YS];
    int t0 = blockIdx.x * XB;
    int tid = threadIdx.x;
    int nv = TM1 - t0; if (nv > XB) nv = XB;

    for (int q = 0; q < nv; ++q) {
        int t = t0 + q;
        s_a[q][tid] = out[OFF_ALPHA + t * YS + tid];
        s_w[q][tid] = g_bx[(t + 1) * YS + tid] * out[OFF_BETA + (t + 1) * YS + tid];
    }
    __syncthreads();

    const float* Ac = A + tid;
    if (nv == XB) {
        float w0 = s_w[0][tid], w1 = s_w[1][tid], w2 = s_w[2][tid], w3 = s_w[3][tid];
        float* o0 = out + OFF_XI + (size_t)(t0 + 0) * YS * YS + tid;
        float* o1 = out + OFF_XI + (size_t)(t0 + 1) * YS * YS + tid;
        float* o2 = out + OFF_XI + (size_t)(t0 + 2) * YS * YS + tid;
        float* o3 = out + OFF_XI + (size_t)(t0 + 3) * YS * YS + tid;
#pragma unroll 4
        for (int i = 0; i < YS; ++i) {
            float av = __ldg(Ac + (size_t)i * YS);
            o0[(size_t)i * YS] = (s_a[0][i] * av) * w0;
            o1[(size_t)i * YS] = (s_a[1][i] * av) * w1;
            o2[(size_t)i * YS] = (s_a[2][i] * av) * w2;
            o3[(size_t)i * YS] = (s_a[3][i] * av) * w3;
        }
    } else {
        for (int q = 0; q < nv; ++q) {
            float wq = s_w[q][tid];
            float* oq = out + OFF_XI + (size_t)(t0 + q) * YS * YS + tid;
#pragma unroll 4
            for (int i = 0; i < YS; ++i) {
                float av = __ldg(Ac + (size_t)i * YS);
                oq[(size_t)i * YS] = (s_a[q][i] * av) * wq;
            }
        }
    }
}

// ---------------------------------------------------------------- launch
extern "C" void kernel_launch(void* const* d_in, const int* in_sizes, int n_in,
                              void* d_out, int out_size) {
    const int*   x  = (const int*)d_in[0];
    const float* A  = (const float*)d_in[1];
    const float* b  = (const float*)d_in[2];
    const float* pi = (const float*)d_in[3];
    float* out = (float*)d_out;

    prep_bx_kernel<<<TS, YS>>>(x, b);
    recur_cluster_kernel<<<24, YS>>>(A, pi, out);
    gamma_kernel<<<TS, YS>>>(out);
    xi_kernel<<<(TM1 + XB - 1) / XB, YS>>>(A, out);
}

// round 9
// speedup vs baseline: 1.4113x; 1.4113x over previous
#include <cuda_runtime.h>

#define YS 256
#define XS 16
#define TS 2048
#define TM1 2047

// Output packing (float32), reference return order:
// alpha (T*Y) | beta (T*Y) | p (1) | gamma (T*Y) | xi ((T-1)*Y*Y) | path (T)
#define OFF_ALPHA 0
#define OFF_BETA  (TS * YS)
#define OFF_P     (2 * TS * YS)
#define OFF_GAMMA (2 * TS * YS + 1)
#define OFF_XI    ((size_t)(3 * TS * YS + 1))
#define OFF_PATH  (OFF_XI + (size_t)TM1 * YS * YS)

#define MSTRIDE 36   // padded row stride (floats): conflict-free LDS.128
#define NSLOT 3      // ring depth 3 (depth 2 races: producer 2 steps ahead)

// Scratch (static device memory — no allocations)
__device__ float g_bx[TS * YS];          // bx[t][j] = b[j, x[t]]
__device__ unsigned char g_bp[TM1 * YS]; // Viterbi backpointers (values 0..255)
__device__ float g_p;

// FTZ multiply — matches reference runtime's flush-to-zero f32 (verified R6).
__device__ __forceinline__ float fmul_ftz(float a, float b) {
    float r;
    asm("mul.rn.ftz.f32 %0, %1, %2;" : "=f"(r) : "f"(a), "f"(b));
    return r;
}

__device__ __forceinline__ unsigned int smem_u32(const void* p) {
    unsigned int a;
    asm("{ .reg .u64 t; cvta.to.shared.u64 t, %1; cvt.u32.u64 %0, t; }"
        : "=r"(a) : "l"(p));
    return a;
}

__device__ __forceinline__ unsigned int ctarank() {
    unsigned int r;
    asm("mov.u32 %0, %%cluster_ctarank;" : "=r"(r));
    return r;
}

// Weak remote v4 store into cluster CTA `rank` (no arrive).
__device__ __forceinline__ void push_quad(unsigned int bufaddr, unsigned int rank,
                                          float4 v) {
    asm volatile(
        "{ .reg .b32 ra;\n\t"
        "mapa.shared::cluster.u32 ra, %0, %1;\n\t"
        "st.shared::cluster.v4.f32 [ra], {%2,%3,%4,%5}; }"
        :: "r"(bufaddr), "r"(rank),
           "f"(v.x), "f"(v.y), "f"(v.z), "f"(v.w) : "memory");
}

// Consolidated per-CTA release-arrive at cluster CTA `rank`'s slot mbarrier.
// Issued AFTER __syncthreads(): cumulativity makes every warp's prior remote
// stores visible to any consumer that acquires this mbarrier.
__device__ __forceinline__ void arrive_remote(unsigned int mbaraddr, unsigned int rank) {
    asm volatile(
        "{ .reg .b32 rb;\n\t"
        "mapa.shared::cluster.u32 rb, %0, %1;\n\t"
        "mbarrier.arrive.release.cluster.shared::cluster.b64 _, [rb]; }"
        :: "r"(mbaraddr), "r"(rank) : "memory");
}

// Consumer: parity wait with cluster-scope acquire (DSMEM-written data).
__device__ __forceinline__ void mbar_wait(unsigned int addr, unsigned int parity) {
    asm volatile(
        "{ .reg .pred P;\n\t"
        "WL%=:\n\t"
        "mbarrier.try_wait.parity.acquire.cluster.shared::cta.b64 P, [%0], %1, 0x989680;\n\t"
        "@P bra WD%=;\n\t"
        "bra WL%=;\n\t"
        "WD%=: }"
        :: "r"(addr), "r"(parity) : "memory");
}

#define CLUSTER_ARRIVE() asm volatile("barrier.cluster.arrive.aligned;" ::: "memory")
#define CLUSTER_WAIT()   asm volatile("barrier.cluster.wait.aligned;" ::: "memory")

// ---------------------------------------------------------------- prep
__global__ void prep_bx_kernel(const int* __restrict__ x,
                               const float* __restrict__ b) {
    int t = blockIdx.x;
    int j = threadIdx.x;
    g_bx[t * YS + j] = b[j * XS + x[t]];
}

// ---------------------------------------------------------------- recurrences
// grid = 24 CTAs = 3 clusters of 8. Cluster r: 0=alpha, 1=beta, 2=Viterbi.
// CTA g owns output columns [g*32, g*32+32); matrix slice in SMEM. Per step:
// compute 32 outputs from local copy of the full 256-vector; warps weak-push
// quads into all 8 CTAs' next-slot buffer; __syncthreads; warp 0 issues ONE
// release-arrive per target CTA (slot mbarrier count = 8). Consumers
// acquire-wait the slot mbarrier at the top of the next step.
__global__ void __cluster_dims__(8, 1, 1)
recur_cluster_kernel(const float* __restrict__ A,
                     const float* __restrict__ pi,
                     float* __restrict__ out) {
    __shared__ __align__(16) float Ms[YS * MSTRIDE];       // 36 KB slice
    __shared__ __align__(16) float s_buf[NSLOT][YS];       // slot ring
    __shared__ __align__(8) unsigned long long s_mbar[NSLOT];
    __shared__ unsigned int s_redu[8];
    __shared__ float s_redf[8];
    __shared__ int s_dead;
    __shared__ int s_last;

    const int tid  = threadIdx.x;
    const int w    = tid >> 5;
    const int lane = tid & 31;
    const int c0   = w * 4;                 // local column quad
    const unsigned int g = ctarank();
    const int r    = blockIdx.x >> 3;       // recursion id
    const int colg = (int)g * 32 + c0;      // global column base of this warp

    const unsigned int bufu  = smem_u32(&s_buf[0][0]);
    const unsigned int mbaru = smem_u32(&s_mbar[0]);

    // ---- init mbarriers (count 8 = one consolidated arrive per source CTA)
    if (tid == 0) {
#pragma unroll
        for (int sl = 0; sl < NSLOT; ++sl)
            asm volatile("mbarrier.init.shared.b64 [%0], 8;"
                         :: "r"(mbaru + sl * 8) : "memory");
        s_dead = 0;
        s_last = 0;
    }

    // ---- load matrix slice into SMEM ----
    if (r != 1) {
        // alpha/viterbi: Ms[k][c] = A[k][g*32+c]   (out_c = sum_k v[k]*A[k][c])
        for (int idx = tid; idx < YS * 32; idx += YS) {
            int k = idx >> 5, c = idx & 31;
            Ms[k * MSTRIDE + c] = A[k * YS + (int)g * 32 + c];
        }
    } else {
        // beta: Ms[k][c] = A[g*32+c][k]            (out_c = sum_k w[k]*A[c][k])
        for (int cc = 0; cc < 32; ++cc)
            Ms[tid * MSTRIDE + cc] = A[((int)g * 32 + cc) * YS + tid];
    }

    // ---- init v0 (slot 0, local) and boundary rows ----
    if (r == 0) {
        float a0 = g_bx[tid] * pi[tid];
        s_buf[0][tid] = a0;
        if (g == 0) out[OFF_ALPHA + tid] = a0;
    } else if (r == 1) {
        s_buf[0][tid] = g_bx[(TS - 1) * YS + tid];   // w[T-1] = bx[T-1] * 1
        if (g == 0) out[OFF_BETA + (TS - 1) * YS + tid] = 1.0f;
    } else {
        s_buf[0][tid] = g_bx[tid] * pi[tid];
    }
    __syncthreads();
    CLUSTER_ARRIVE();   // all mbars initialized before any remote arrive
    CLUSTER_WAIT();

    const int S = TS - 1;  // 2047 steps
    int tz = -1;
    unsigned int ph0 = 0, ph1 = 0, ph2 = 0;  // per-slot parity

    // bx prefetch for step 0
    int t0 = (r == 1) ? (TS - 2) : 1;
    float4 bxv = __ldg((const float4*)&g_bx[t0 * YS + colg]);

    for (int s = 0; s < S; ++s) {
        const int slot = s % NSLOT;
        const int slot2 = (s + 1) % NSLOT;
        const int t = (r == 1) ? (TS - 2 - s) : (s + 1);

        // wait for this step's input (step 0's input is local)
        if (s > 0) {
            unsigned int p = (slot == 0) ? ph0 : (slot == 1 ? ph1 : ph2);
            mbar_wait(mbaru + slot * 8, p);
            if (slot == 0) ph0 ^= 1u; else if (slot == 1) ph1 ^= 1u; else ph2 ^= 1u;
        }

        // gather v into registers (k = kk*32 + lane)
        float vreg[8];
        unsigned int orv = 0u;
#pragma unroll
        for (int kk = 0; kk < 8; ++kk) {
            vreg[kk] = s_buf[slot][kk * 32 + lane];
            orv |= __float_as_uint(vreg[kk]);
        }

        if (r == 2) {
            // all-zero detection (identical buffers in every CTA -> uniform)
            unsigned int o = __reduce_or_sync(0xffffffffu, orv);
            if (lane == 0) s_redu[w] = o;
            __syncthreads();
            if (tid == 0) {
                unsigned int oo = 0u;
                for (int i = 0; i < 8; ++i) oo |= s_redu[i];
                if (oo == 0u) s_dead = 1;
            }
            __syncthreads();
            if (s_dead) { tz = s; break; }
        }

        const unsigned int nbuf = bufu + (unsigned int)(slot2 * YS + colg) * 4u;
        const unsigned int nmb  = mbaru + slot2 * 8;

        if (r != 2) {
            float4 acc = make_float4(0.f, 0.f, 0.f, 0.f);
#pragma unroll
            for (int kk = 0; kk < 8; ++kk) {
                float vv = vreg[kk];
                float4 m = *(const float4*)&Ms[(kk * 32 + lane) * MSTRIDE + c0];
                acc.x = fmaf(vv, m.x, acc.x);
                acc.y = fmaf(vv, m.y, acc.y);
                acc.z = fmaf(vv, m.z, acc.z);
                acc.w = fmaf(vv, m.w, acc.w);
            }
#pragma unroll
            for (int off = 16; off > 0; off >>= 1) {
                acc.x += __shfl_xor_sync(0xffffffffu, acc.x, off);
                acc.y += __shfl_xor_sync(0xffffffffu, acc.y, off);
                acc.z += __shfl_xor_sync(0xffffffffu, acc.z, off);
                acc.w += __shfl_xor_sync(0xffffffffu, acc.w, off);
            }
            // pushed value includes the bx factor for the NEXT step
            float4 push;
            push.x = acc.x * bxv.x;
            push.y = acc.y * bxv.y;
            push.z = acc.z * bxv.z;
            push.w = acc.w * bxv.w;
            if (lane < 8)
                push_quad(nbuf, lane, push);
            if (lane == 8) {
                if (r == 0)
                    *(float4*)&out[OFF_ALPHA + t * YS + colg] = push;  // alpha = sum*bx
                else
                    *(float4*)&out[OFF_BETA + t * YS + colg] = acc;   // beta raw
            }
        } else {
            // Viterbi: max/argmax over k, FTZ muls, first-max tie semantics
            unsigned int bu[4] = {0u, 0u, 0u, 0u};
            int bi[4] = {lane, lane, lane, lane};
#pragma unroll
            for (int kk = 0; kk < 8; ++kk) {
                int k = kk * 32 + lane;
                float vv = vreg[kk];
                float4 m = *(const float4*)&Ms[k * MSTRIDE + c0];
                unsigned int s0 = __float_as_uint(fmul_ftz(vv, m.x));
                unsigned int s1 = __float_as_uint(fmul_ftz(vv, m.y));
                unsigned int s2 = __float_as_uint(fmul_ftz(vv, m.z));
                unsigned int s3 = __float_as_uint(fmul_ftz(vv, m.w));
                if (s0 > bu[0]) { bu[0] = s0; bi[0] = k; }
                if (s1 > bu[1]) { bu[1] = s1; bi[1] = k; }
                if (s2 > bu[2]) { bu[2] = s2; bi[2] = k; }
                if (s3 > bu[3]) { bu[3] = s3; bi[3] = k; }
            }
#pragma unroll
            for (int off = 16; off > 0; off >>= 1) {
#pragma unroll
                for (int j = 0; j < 4; ++j) {
                    unsigned int ou = __shfl_xor_sync(0xffffffffu, bu[j], off);
                    int oi = __shfl_xor_sync(0xffffffffu, bi[j], off);
                    if (ou > bu[j] || (ou == bu[j] && oi < bi[j])) {
                        bu[j] = ou; bi[j] = oi;
                    }
                }
            }
            float4 push;
            push.x = fmul_ftz(bxv.x, __uint_as_float(bu[0]));
            push.y = fmul_ftz(bxv.y, __uint_as_float(bu[1]));
            push.z = fmul_ftz(bxv.z, __uint_as_float(bu[2]));
            push.w = fmul_ftz(bxv.w, __uint_as_float(bu[3]));
            if (lane < 8)
                push_quad(nbuf, lane, push);
            if (lane == 8) {
                unsigned int pack = (unsigned int)bi[0] | ((unsigned int)bi[1] << 8)
                                  | ((unsigned int)bi[2] << 16) | ((unsigned int)bi[3] << 24);
                *(unsigned int*)(g_bp + (size_t)(t - 1) * YS + colg) = pack;
            }
        }

        // all warps' remote stores done issuing -> consolidated release-arrives
        __syncthreads();
        if (w == 0 && lane < 8)
            arrive_remote(nmb, lane);

        if (s + 1 < S) {
            int tn = (r == 1) ? (TS - 2 - (s + 1)) : (s + 2);
            bxv = __ldg((const float4*)&g_bx[tn * YS + colg]);
        }
    }

    // ---- epilogues ----
    if (r == 0) {
        // p = sum(alpha[T-1]): final vector pushed into slot S%NSLOT
        if (g == 0) {
            const int fslot = S % NSLOT;
            unsigned int p = (fslot == 0) ? ph0 : (fslot == 1 ? ph1 : ph2);
            mbar_wait(mbaru + fslot * 8, p);
            float v = s_buf[fslot][tid];
#pragma unroll
            for (int off = 16; off > 0; off >>= 1)
                v += __shfl_xor_sync(0xffffffffu, v, off);
            if (lane == 0) s_redf[w] = v;
            __syncthreads();
            if (tid == 0) {
                float pp = 0.f;
                for (int i = 0; i < 8; ++i) pp += s_redf[i];
                out[OFF_P] = pp;
                g_p = pp;
            }
        }
    } else if (r == 2) {
        // zero-fill bp rows [tz, TM1) across the cluster (V dead from tz on)
        if (tz >= 0) {
            unsigned int* bp32 = (unsigned int*)(g_bp + (size_t)tz * YS);
            int n32 = (TM1 - tz) * (YS / 4);
            for (int i = (int)g * YS + tid; i < n32; i += 8 * YS) bp32[i] = 0u;
        }
        CLUSTER_ARRIVE();
        CLUSTER_WAIT();
        if (g == 0) {
            if (tz >= 0) {
                for (int k = tz + tid; k < TS - 1; k += YS)
                    out[OFF_PATH + k] = 0.0f;
                // s_last already 0
            } else if (tid == 0) {
                const int fslot = S % NSLOT;
                unsigned int p = (fslot == 0) ? ph0 : (fslot == 1 ? ph1 : ph2);
                mbar_wait(mbaru + fslot * 8, p);
                unsigned int m = __float_as_uint(s_buf[fslot][0]);
                int idx = 0;
                for (int i = 1; i < YS; ++i) {
                    unsigned int vi = __float_as_uint(s_buf[fslot][i]);
                    if (vi > m) { m = vi; idx = i; }
                }
                s_last = idx;
            }
            __syncthreads();
            if (tid == 0) {
                int last = s_last;
                out[OFF_PATH + TS - 1] = (float)last;
                int st = last;
                int tstart = (tz >= 0) ? (tz - 1) : (TS - 2);
                for (int t = tstart; t >= 0; --t) {
                    st = (int)g_bp[(size_t)t * YS + st];
                    out[OFF_PATH + t] = (float)st;
                }
            }
        }
    }

    // collective exit: no CTA leaves while in-flight DSMEM ops may target it
    CLUSTER_ARRIVE();
    CLUSTER_WAIT();
}

// ---------------------------------------------------------------- gamma
__global__ void gamma_kernel(float* __restrict__ out) {
    int idx = blockIdx.x * YS + threadIdx.x;
    float p = g_p;
    out[OFF_GAMMA + idx] = out[OFF_ALPHA + idx] * out[OFF_BETA + idx] / p;
}

// ---------------------------------------------------------------- xi
// (R7-proven version: 188 us.) block t in [0, T-2];
// xi[t][i][j] = (alpha[t][i] * A[i][j]) * (bx[t+1][j]*beta[t+1][j])
// OFF_XI is an odd float offset -> region 4B-aligned -> scalar STG.32 only.
__global__ void xi_kernel(const float* __restrict__ A, float* __restrict__ out) {
    __shared__ __align__(16) float s_a[YS];
    __shared__ __align__(16) float s_w[YS];
    int t = blockIdx.x;
    int tid = threadIdx.x;

    s_a[tid] = out[OFF_ALPHA + t * YS + tid];
    s_w[tid] = g_bx[(t + 1) * YS + tid] * out[OFF_BETA + (t + 1) * YS + tid];
    __syncthreads();

    float wj = s_w[tid];
    float* ob = out + OFF_XI + (size_t)t * YS * YS + tid;
    const float* Ac = A + tid;
#pragma unroll 8
    for (int i = 0; i < YS; ++i) {
        float ai = s_a[i];
        float av = __ldg(Ac + (size_t)i * YS);
        ob[(size_t)i * YS] = (ai * av) * wj;
    }
}

// ---------------------------------------------------------------- launch
extern "C" void kernel_launch(void* const* d_in, const int* in_sizes, int n_in,
                              void* d_out, int out_size) {
    const int*   x  = (const int*)d_in[0];
    const float* A  = (const float*)d_in[1];
    const float* b  = (const float*)d_in[2];
    const float* pi = (const float*)d_in[3];
    float* out = (float*)d_out;

    prep_bx_kernel<<<TS, YS>>>(x, b);
    recur_cluster_kernel<<<24, YS>>>(A, pi, out);
    gamma_kernel<<<TS, YS>>>(out);
    xi_kernel<<<TM1, YS>>>(A, out);
}

// round 11
// speedup vs baseline: 1.7475x; 1.2382x over previous
#include <cuda_runtime.h>

#define YS 256
#define XS 16
#define TS 2048
#define TM1 2047

// Output packing (float32), reference return order:
// alpha (T*Y) | beta (T*Y) | p (1) | gamma (T*Y) | xi ((T-1)*Y*Y) | path (T)
#define OFF_ALPHA 0
#define OFF_BETA  (TS * YS)
#define OFF_P     (2 * TS * YS)
#define OFF_GAMMA (2 * TS * YS + 1)
#define OFF_XI    ((size_t)(3 * TS * YS + 1))
#define OFF_PATH  (OFF_XI + (size_t)TM1 * YS * YS)

#define NSLOT 3      // ring depth 3 (safe under <=1-step warp skew; see proof in notes)

// Scratch (static device memory — no allocations)
__device__ float g_bx[TS * YS];          // bx[t][j] = b[j, x[t]]
__device__ unsigned char g_bp[TM1 * YS]; // Viterbi backpointers (values 0..255)
__device__ float g_p;

// FTZ multiply — matches reference runtime's flush-to-zero f32 (verified R6).
__device__ __forceinline__ float fmul_ftz(float a, float b) {
    float r;
    asm("mul.rn.ftz.f32 %0, %1, %2;" : "=f"(r) : "f"(a), "f"(b));
    return r;
}

__device__ __forceinline__ unsigned int smem_u32(const void* p) {
    unsigned int a;
    asm("{ .reg .u64 t; cvta.to.shared.u64 t, %1; cvt.u32.u64 %0, t; }"
        : "=r"(a) : "l"(p));
    return a;
}

__device__ __forceinline__ unsigned int ctarank() {
    unsigned int r;
    asm("mov.u32 %0, %%cluster_ctarank;" : "=r"(r));
    return r;
}

// Weak remote v4 store into cluster CTA `rank`.
__device__ __forceinline__ void push_quad(unsigned int bufaddr, unsigned int rank,
                                          float4 v) {
    asm volatile(
        "{ .reg .b32 ra;\n\t"
        "mapa.shared::cluster.u32 ra, %0, %1;\n\t"
        "st.shared::cluster.v4.f32 [ra], {%2,%3,%4,%5}; }"
        :: "r"(bufaddr), "r"(rank),
           "f"(v.x), "f"(v.y), "f"(v.z), "f"(v.w) : "memory");
}

// Release flag store (same thread as its data store -> orders data before flag
// for any consumer that acquires this flag).
__device__ __forceinline__ void flag_release(unsigned int flagaddr, unsigned int rank,
                                             unsigned int val) {
    asm volatile(
        "{ .reg .b32 rb;\n\t"
        "mapa.shared::cluster.u32 rb, %0, %1;\n\t"
        "st.release.cluster.shared::cluster.b32 [rb], %2; }"
        :: "r"(flagaddr), "r"(rank), "r"(val) : "memory");
}

__device__ __forceinline__ unsigned int ld_acq(unsigned int addr) {
    unsigned int v;
    asm volatile("ld.acquire.cluster.shared::cta.b32 %0, [%1];"
                 : "=r"(v) : "r"(addr) : "memory");
    return v;
}

#define CLUSTER_ARRIVE() asm volatile("barrier.cluster.arrive.aligned;" ::: "memory")
#define CLUSTER_WAIT()   asm volatile("barrier.cluster.wait.aligned;" ::: "memory")

// ---------------------------------------------------------------- prep
__global__ void prep_bx_kernel(const int* __restrict__ x,
                               const float* __restrict__ b) {
    int t = blockIdx.x;
    int j = threadIdx.x;
    g_bx[t * YS + j] = b[j * XS + x[t]];
}

// ---------------------------------------------------------------- recurrences
// grid = 24 CTAs = 3 clusters of 8. Cluster r: 0=alpha, 1=beta, 2=Viterbi.
// CTA g owns output columns [g*32, g*32+32); its A-slice lives in REGISTERS
// (32 floats/thread). Steady state has NO barrier.cluster / mbarrier /
// __syncthreads (alpha/beta): warps push quads + per-(srcCTA,srcWarp) release
// flags into all 8 CTAs' next-slot ring buffer; each consumer warp acquire-
// polls all 64 flags of its input slot. Warp skew <= 1 step; ring depth 3.
__global__ void __cluster_dims__(8, 1, 1)
recur_cluster_kernel(const float* __restrict__ A,
                     const float* __restrict__ pi,
                     float* __restrict__ out) {
    __shared__ __align__(16) float s_buf[NSLOT][YS];           // slot ring
    __shared__ __align__(16) unsigned int s_flags[NSLOT * 64]; // [slot][srcCTA*8+srcWarp]
    __shared__ unsigned int s_redu[8];
    __shared__ float s_redf[8];
    __shared__ int s_dead;
    __shared__ int s_last;

    const int tid  = threadIdx.x;
    const int w    = tid >> 5;
    const int lane = tid & 31;
    const int c0   = w * 4;                 // local column quad
    const unsigned int g = ctarank();
    const int r    = blockIdx.x >> 3;       // recursion id
    const int colg = (int)g * 32 + c0;      // global column base of this warp

    const unsigned int bufu  = smem_u32(&s_buf[0][0]);
    const unsigned int flagu = smem_u32(&s_flags[0]);

    // ---- zero flags ----
    if (tid < NSLOT * 64) s_flags[tid] = 0u;
    if (tid == 0) { s_dead = 0; s_last = 0; }

    // ---- A slice into registers: areg[kk] pairs with v[k], k = kk*32+lane ----
    float4 areg[8];
    if (r != 1) {
        // alpha/viterbi: areg[kk] = A[k][colg..colg+3]
#pragma unroll
        for (int kk = 0; kk < 8; ++kk)
            areg[kk] = __ldg((const float4*)(A + (size_t)(kk * 32 + lane) * YS + colg));
    } else {
        // beta: areg[kk].c = A[colg+c][k]
#pragma unroll
        for (int kk = 0; kk < 8; ++kk) {
            int k = kk * 32 + lane;
            areg[kk].x = __ldg(A + (size_t)(colg + 0) * YS + k);
            areg[kk].y = __ldg(A + (size_t)(colg + 1) * YS + k);
            areg[kk].z = __ldg(A + (size_t)(colg + 2) * YS + k);
            areg[kk].w = __ldg(A + (size_t)(colg + 3) * YS + k);
        }
    }

    // ---- init v0 (slot 0) and boundary rows ----
    if (r == 0) {
        float a0 = g_bx[tid] * pi[tid];
        s_buf[0][tid] = a0;
        if (g == 0) out[OFF_ALPHA + tid] = a0;
    } else if (r == 1) {
        s_buf[0][tid] = g_bx[(TS - 1) * YS + tid];   // w[T-1] = bx[T-1] * 1
        if (g == 0) out[OFF_BETA + (TS - 1) * YS + tid] = 1.0f;
    } else {
        s_buf[0][tid] = g_bx[tid] * pi[tid];
    }
    __syncthreads();
    CLUSTER_ARRIVE();   // flags zeroed + slot0 ready before any remote traffic
    CLUSTER_WAIT();

    const int S = TS - 1;  // 2047 steps
    int tz = -1;

    // this lane's two flag slots to poll (ids: lane and lane+32 of 64)
    // bx prefetch for step 0
    int t0 = (r == 1) ? (TS - 2) : 1;
    float4 bxv = __ldg((const float4*)&g_bx[t0 * YS + colg]);

    for (int s = 0; s < S; ++s) {
        const int slot = s % NSLOT;
        const int slot2 = (s + 1) % NSLOT;
        const int t = (r == 1) ? (TS - 2 - s) : (s + 1);

        // wait for this step's input (step 0's input is local)
        if (s > 0) {
            const unsigned int fa = flagu + (unsigned int)(slot * 64 + lane) * 4u;
            const unsigned int fb = fa + 32u * 4u;
            const unsigned int need = (unsigned int)s;
            bool ok;
            do {
                ok = (ld_acq(fa) >= need) && (ld_acq(fb) >= need);
            } while (!__all_sync(0xffffffffu, ok));
        }

        // gather v into registers (k = kk*32 + lane)
        float vreg[8];
        unsigned int orv = 0u;
#pragma unroll
        for (int kk = 0; kk < 8; ++kk) {
            vreg[kk] = s_buf[slot][kk * 32 + lane];
            orv |= __float_as_uint(vreg[kk]);
        }

        if (r == 2) {
            // all-zero detection (identical buffers in every CTA -> uniform)
            unsigned int o = __reduce_or_sync(0xffffffffu, orv);
            if (lane == 0) s_redu[w] = o;
            __syncthreads();
            if (tid == 0) {
                unsigned int oo = 0u;
                for (int i = 0; i < 8; ++i) oo |= s_redu[i];
                if (oo == 0u) s_dead = 1;
            }
            __syncthreads();
            if (s_dead) { tz = s; break; }
        }

        const unsigned int nbuf  = bufu + (unsigned int)(slot2 * YS + colg) * 4u;
        const unsigned int nflag = flagu + (unsigned int)(slot2 * 64 + (int)g * 8 + w) * 4u;
        const unsigned int tag = (unsigned int)(s + 1);

        if (r != 2) {
            float4 acc = make_float4(0.f, 0.f, 0.f, 0.f);
#pragma unroll
            for (int kk = 0; kk < 8; ++kk) {
                float vv = vreg[kk];
                acc.x = fmaf(vv, areg[kk].x, acc.x);
                acc.y = fmaf(vv, areg[kk].y, acc.y);
                acc.z = fmaf(vv, areg[kk].z, acc.z);
                acc.w = fmaf(vv, areg[kk].w, acc.w);
            }
#pragma unroll
            for (int off = 16; off > 0; off >>= 1) {
                acc.x += __shfl_xor_sync(0xffffffffu, acc.x, off);
                acc.y += __shfl_xor_sync(0xffffffffu, acc.y, off);
                acc.z += __shfl_xor_sync(0xffffffffu, acc.z, off);
                acc.w += __shfl_xor_sync(0xffffffffu, acc.w, off);
            }
            // pushed value includes the bx factor for the NEXT step
            float4 push;
            push.x = acc.x * bxv.x;
            push.y = acc.y * bxv.y;
            push.z = acc.z * bxv.z;
            push.w = acc.w * bxv.w;
            if (lane < 8) {
                push_quad(nbuf, lane, push);
                flag_release(nflag, lane, tag);
            }
            if (lane == 8) {
                if (r == 0)
                    *(float4*)&out[OFF_ALPHA + t * YS + colg] = push;  // alpha = sum*bx
                else
                    *(float4*)&out[OFF_BETA + t * YS + colg] = acc;   // beta raw
            }
        } else {
            // Viterbi: max/argmax over k, FTZ muls, first-max tie semantics
            unsigned int bu[4] = {0u, 0u, 0u, 0u};
            int bi[4] = {lane, lane, lane, lane};
#pragma unroll
            for (int kk = 0; kk < 8; ++kk) {
                int k = kk * 32 + lane;
                float vv = vreg[kk];
                unsigned int s0 = __float_as_uint(fmul_ftz(vv, areg[kk].x));
                unsigned int s1 = __float_as_uint(fmul_ftz(vv, areg[kk].y));
                unsigned int s2 = __float_as_uint(fmul_ftz(vv, areg[kk].z));
                unsigned int s3 = __float_as_uint(fmul_ftz(vv, areg[kk].w));
                if (s0 > bu[0]) { bu[0] = s0; bi[0] = k; }
                if (s1 > bu[1]) { bu[1] = s1; bi[1] = k; }
                if (s2 > bu[2]) { bu[2] = s2; bi[2] = k; }
                if (s3 > bu[3]) { bu[3] = s3; bi[3] = k; }
            }
#pragma unroll
            for (int off = 16; off > 0; off >>= 1) {
#pragma unroll
                for (int j = 0; j < 4; ++j) {
                    unsigned int ou = __shfl_xor_sync(0xffffffffu, bu[j], off);
                    int oi = __shfl_xor_sync(0xffffffffu, bi[j], off);
                    if (ou > bu[j] || (ou == bu[j] && oi < bi[j])) {
                        bu[j] = ou; bi[j] = oi;
                    }
                }
            }
            float4 push;
            push.x = fmul_ftz(bxv.x, __uint_as_float(bu[0]));
            push.y = fmul_ftz(bxv.y, __uint_as_float(bu[1]));
            push.z = fmul_ftz(bxv.z, __uint_as_float(bu[2]));
            push.w = fmul_ftz(bxv.w, __uint_as_float(bu[3]));
            if (lane < 8) {
                push_quad(nbuf, lane, push);
                flag_release(nflag, lane, tag);
            }
            if (lane == 8) {
                unsigned int pack = (unsigned int)bi[0] | ((unsigned int)bi[1] << 8)
                                  | ((unsigned int)bi[2] << 16) | ((unsigned int)bi[3] << 24);
                *(unsigned int*)(g_bp + (size_t)(t - 1) * YS + colg) = pack;
            }
        }

        if (s + 1 < S) {
            int tn = (r == 1) ? (TS - 2 - (s + 1)) : (s + 2);
            bxv = __ldg((const float4*)&g_bx[tn * YS + colg]);
        }
    }

    // ---- epilogues ----
    if (r == 0) {
        // p = sum(alpha[T-1]): final vector is in slot S%NSLOT (flag value S)
        if (g == 0) {
            const int fslot = S % NSLOT;
            const unsigned int fa = flagu + (unsigned int)(fslot * 64 + lane) * 4u;
            const unsigned int fb = fa + 32u * 4u;
            bool ok;
            do {
                ok = (ld_acq(fa) >= (unsigned int)S) && (ld_acq(fb) >= (unsigned int)S);
            } while (!__all_sync(0xffffffffu, ok));
            float v = s_buf[fslot][tid];
#pragma unroll
            for (int off = 16; off > 0; off >>= 1)
                v += __shfl_xor_sync(0xffffffffu, v, off);
            if (lane == 0) s_redf[w] = v;
            __syncthreads();
            if (tid == 0) {
                float pp = 0.f;
                for (int i = 0; i < 8; ++i) pp += s_redf[i];
                out[OFF_P] = pp;
                g_p = pp;
            }
        }
    } else if (r == 2) {
        // zero-fill bp rows [tz, TM1) across the cluster (V dead from tz on)
        if (tz >= 0) {
            unsigned int* bp32 = (unsigned int*)(g_bp + (size_t)tz * YS);
            int n32 = (TM1 - tz) * (YS / 4);
            for (int i = (int)g * YS + tid; i < n32; i += 8 * YS) bp32[i] = 0u;
        }
        CLUSTER_ARRIVE();
        CLUSTER_WAIT();
        if (g == 0) {
            if (tz >= 0) {
                for (int k = tz + tid; k < TS - 1; k += YS)
                    out[OFF_PATH + k] = 0.0f;
                // s_last already 0
            } else if (w == 0) {
                const int fslot = S % NSLOT;
                const unsigned int fa = flagu + (unsigned int)(fslot * 64 + lane) * 4u;
                const unsigned int fb = fa + 32u * 4u;
                bool ok;
                do {
                    ok = (ld_acq(fa) >= (unsigned int)S) && (ld_acq(fb) >= (unsigned int)S);
                } while (!__all_sync(0xffffffffu, ok));
                if (lane == 0) {
                    unsigned int m = __float_as_uint(s_buf[fslot][0]);
                    int idx = 0;
                    for (int i = 1; i < YS; ++i) {
                        unsigned int vi = __float_as_uint(s_buf[fslot][i]);
                        if (vi > m) { m = vi; idx = i; }
                    }
                    s_last = idx;
                }
            }
            __syncthreads();
            if (tid == 0) {
                int last = s_last;
                out[OFF_PATH + TS - 1] = (float)last;
                int st = last;
                int tstart = (tz >= 0) ? (tz - 1) : (TS - 2);
                for (int t = tstart; t >= 0; --t) {
                    st = (int)g_bp[(size_t)t * YS + st];
                    out[OFF_PATH + t] = (float)st;
                }
            }
        }
    }

    // collective exit: no CTA leaves while in-flight DSMEM ops may target it
    CLUSTER_ARRIVE();
    CLUSTER_WAIT();
}

// ---------------------------------------------------------------- gamma
__global__ void gamma_kernel(float* __restrict__ out) {
    int idx = blockIdx.x * YS + threadIdx.x;
    float p = g_p;
    out[OFF_GAMMA + idx] = out[OFF_ALPHA + idx] * out[OFF_BETA + idx] / p;
}

// ---------------------------------------------------------------- xi
// (R7-proven version: ~187 us.) block t in [0, T-2];
// xi[t][i][j] = (alpha[t][i] * A[i][j]) * (bx[t+1][j]*beta[t+1][j])
// OFF_XI is an odd float offset -> region 4B-aligned -> scalar STG.32 only.
__global__ void xi_kernel(const float* __restrict__ A, float* __restrict__ out) {
    __shared__ __align__(16) float s_a[YS];
    __shared__ __align__(16) float s_w[YS];
    int t = blockIdx.x;
    int tid = threadIdx.x;

    s_a[tid] = out[OFF_ALPHA + t * YS + tid];
    s_w[tid] = g_bx[(t + 1) * YS + tid] * out[OFF_BETA + (t + 1) * YS + tid];
    __syncthreads();

    float wj = s_w[tid];
    float* ob = out + OFF_XI + (size_t)t * YS * YS + tid;
    const float* Ac = A + tid;
#pragma unroll 8
    for (int i = 0; i < YS; ++i) {
        float ai = s_a[i];
        float av = __ldg(Ac + (size_t)i * YS);
        ob[(size_t)i * YS] = (ai * av) * wj;
    }
}

// ---------------------------------------------------------------- launch
extern "C" void kernel_launch(void* const* d_in, const int* in_sizes, int n_in,
                              void* d_out, int out_size) {
    const int*   x  = (const int*)d_in[0];
    const float* A  = (const float*)d_in[1];
    const float* b  = (const float*)d_in[2];
    const float* pi = (const float*)d_in[3];
    float* out = (float*)d_out;

    prep_bx_kernel<<<TS, YS>>>(x, b);
    recur_cluster_kernel<<<24, YS>>>(A, pi, out);
    gamma_kernel<<<TS, YS>>>(out);
    xi_kernel<<<TM1, YS>>>(A, out);
}

// round 12
// speedup vs baseline: 8.8555x; 5.0675x over previous
#include <cuda_runtime.h>

#define YS 256
#define XS 16
#define TS 2048
#define TM1 2047
#define CCH 32       // chunks per recursion (L = 64)
#define NSLOT 3      // ring depth 3

// Output packing (float32):
// alpha (T*Y) | beta (T*Y) | p (1) | gamma (T*Y) | xi ((T-1)*Y*Y) | path (T)
#define OFF_ALPHA 0
#define OFF_BETA  (TS * YS)
#define OFF_P     (2 * TS * YS)
#define OFF_GAMMA (2 * TS * YS + 1)
#define OFF_XI    ((size_t)(3 * TS * YS + 1))
#define OFF_PATH  (OFF_XI + (size_t)TM1 * YS * YS)

// Scratch (static device memory)
__device__ float g_bx[TS * YS];
__device__ unsigned char g_bp[TM1 * YS];
__device__ float g_SfA[CCH][2], g_SoA[CCH][2];   // alpha first/overlap sums per (chunk, ctarank)
__device__ float g_SfB[CCH][2], g_SoB[CCH][2];   // beta
__device__ float g_SlA[2];                       // sum alpha(T-1) raw
__device__ float g_kap[CCH], g_lam[CCH];
__device__ float g_p;

// FTZ multiply — matches reference flush-to-zero f32 (bit-verified R6).
__device__ __forceinline__ float fmul_ftz(float a, float b) {
    float r;
    asm("mul.rn.ftz.f32 %0, %1, %2;" : "=f"(r) : "f"(a), "f"(b));
    return r;
}
__device__ __forceinline__ unsigned int smem_u32(const void* p) {
    unsigned int a;
    asm("{ .reg .u64 t; cvta.to.shared.u64 t, %1; cvt.u32.u64 %0, t; }"
        : "=r"(a) : "l"(p));
    return a;
}
__device__ __forceinline__ unsigned int ctarank() {
    unsigned int r;
    asm("mov.u32 %0, %%cluster_ctarank;" : "=r"(r));
    return r;
}
__device__ __forceinline__ void push_quad(unsigned int bufaddr, unsigned int rank,
                                          float4 v) {
    asm volatile(
        "{ .reg .b32 ra;\n\t"
        "mapa.shared::cluster.u32 ra, %0, %1;\n\t"
        "st.shared::cluster.v4.f32 [ra], {%2,%3,%4,%5}; }"
        :: "r"(bufaddr), "r"(rank),
           "f"(v.x), "f"(v.y), "f"(v.z), "f"(v.w) : "memory");
}
__device__ __forceinline__ void flag_release(unsigned int flagaddr, unsigned int rank,
                                             unsigned int val) {
    asm volatile(
        "{ .reg .b32 rb;\n\t"
        "mapa.shared::cluster.u32 rb, %0, %1;\n\t"
        "st.release.cluster.shared::cluster.b32 [rb], %2; }"
        :: "r"(flagaddr), "r"(rank), "r"(val) : "memory");
}
__device__ __forceinline__ unsigned int ld_acq(unsigned int addr) {
    unsigned int v;
    asm volatile("ld.acquire.cluster.shared::cta.b32 %0, [%1];"
                 : "=r"(v) : "r"(addr) : "memory");
    return v;
}
#define CLUSTER_ARRIVE() asm volatile("barrier.cluster.arrive.aligned;" ::: "memory")
#define CLUSTER_WAIT()   asm volatile("barrier.cluster.wait.aligned;" ::: "memory")

// ---------------------------------------------------------------- prep
__global__ void prep_bx_kernel(const int* __restrict__ x,
                               const float* __restrict__ b) {
    int t = blockIdx.x, j = threadIdx.x;
    g_bx[t * YS + j] = b[j * XS + x[t]];
}

// ---------------------------------------------------------------- chunk kernel
// grid = 130 CTAs = 65 clusters of 2, 512 threads.
// pair 0: exact serial Viterbi (early exit at underflow).
// pairs 1..32: alpha chunk c = pair-1.  pairs 33..64: beta chunk c = pair-33.
// Each CTA r of a pair owns output columns [r*128, r*128+128); its A-half is in
// REGISTERS (64 floats/thread). Per step both CTAs exchange their 128-vector
// halves via DSMEM ring + per-warp release flags (R11-proven protocol).
// Chunks c>=1 (alpha) / c<=30 (beta) warm up W=32 steps from an arbitrary
// positive vector (direction converges at (lambda2)^W << fp32 eps); scales are
// stitched later from overlap sums.
__global__ void __cluster_dims__(2, 1, 1) __launch_bounds__(512, 1)
chunk_kernel(const float* __restrict__ A,
             const float* __restrict__ pi,
             float* __restrict__ out) {
    __shared__ __align__(16) float s_buf[NSLOT][YS];
    __shared__ __align__(16) unsigned int s_flags[NSLOT][32]; // [slot][srcCTA*16+warp]
    __shared__ float s_redf[16];
    __shared__ unsigned int s_redu[16];
    __shared__ int s_dead, s_last;

    const int tid  = threadIdx.x;
    const int w    = tid >> 5;           // 0..15
    const int lane = tid & 31;
    const unsigned int r = ctarank();
    const int pair = blockIdx.x >> 1;
    const int mode = (pair == 0) ? 2 : (pair <= CCH ? 0 : 1);
    const int c    = (pair == 0) ? 0 : (pair <= CCH ? pair - 1 : pair - 1 - CCH);
    const int cbase = (int)r * 128 + w * 8;      // this warp's 8 output columns

    const unsigned int bufu  = smem_u32(&s_buf[0][0]);
    const unsigned int flagu = smem_u32(&s_flags[0][0]);

    if (tid < NSLOT * 32) ((unsigned int*)s_flags)[tid] = 0u;
    if (tid == 0) { s_dead = 0; s_last = 0; }

    // ---- A half into registers: k = kk*32+lane pairs with v[k] ----
    float4 aqA[8], aqB[8];
    if (mode != 1) {
        // forward form: out_c = sum_k v[k] * A[k][c]
#pragma unroll
        for (int kk = 0; kk < 8; ++kk) {
            aqA[kk] = __ldg((const float4*)(A + (size_t)(kk * 32 + lane) * YS + cbase));
            aqB[kk] = __ldg((const float4*)(A + (size_t)(kk * 32 + lane) * YS + cbase + 4));
        }
    } else {
        // beta form: out_c = sum_k A[c][k] * w[k]
#pragma unroll
        for (int kk = 0; kk < 8; ++kk) {
            int k = kk * 32 + lane;
            aqA[kk].x = __ldg(A + (size_t)(cbase + 0) * YS + k);
            aqA[kk].y = __ldg(A + (size_t)(cbase + 1) * YS + k);
            aqA[kk].z = __ldg(A + (size_t)(cbase + 2) * YS + k);
            aqA[kk].w = __ldg(A + (size_t)(cbase + 3) * YS + k);
            aqB[kk].x = __ldg(A + (size_t)(cbase + 4) * YS + k);
            aqB[kk].y = __ldg(A + (size_t)(cbase + 5) * YS + k);
            aqB[kk].z = __ldg(A + (size_t)(cbase + 6) * YS + k);
            aqB[kk].w = __ldg(A + (size_t)(cbase + 7) * YS + k);
        }
    }

    // ---- step count and t-mapping ----
    int nsteps, tbase;  // mode0/2: t = tbase + s ; mode1: t = tbase - s
    if (mode == 0) {
        nsteps = (c == 0) ? 64 : (c == CCH - 1 ? 95 : 96);
        tbase  = (c == 0) ? 1 : (64 * c - 31);
    } else if (mode == 1) {
        nsteps = (c == CCH - 1) ? 64 : (c == 0 ? 95 : 96);
        tbase  = (c == CCH - 1) ? 2046 : (64 * c + 94);
    } else {
        nsteps = TM1;
        tbase  = 1;
    }

    // ---- initial vector (slot 0) + exact boundary writes ----
    if (tid < YS) {
        float v;
        if (mode == 0) {
            v = (c == 0) ? g_bx[tid] * pi[tid] : 1.0f;
            if (c == 0 && r == 0) out[OFF_ALPHA + tid] = v;
        } else if (mode == 1) {
            if (c == CCH - 1) {
                v = g_bx[(TS - 1) * YS + tid];      // w(T-1)=bx(T-1)*1, exact
                if (r == 0) out[OFF_BETA + (TS - 1) * YS + tid] = 1.0f;
            } else v = 1.0f;
        } else {
            v = g_bx[tid] * pi[tid];
        }
        s_buf[0][tid] = v;
    }
    __syncthreads();
    CLUSTER_ARRIVE();
    CLUSTER_WAIT();

    int tz = -1;
    int t = (mode == 1) ? tbase : tbase;
    float4 bxA = __ldg((const float4*)&g_bx[t * YS + cbase]);
    float4 bxB = __ldg((const float4*)&g_bx[t * YS + cbase + 4]);

    for (int s = 0; s < nsteps; ++s) {
        const int slot  = s % NSLOT;
        const int slot2 = (s + 1) % NSLOT;
        t = (mode == 1) ? (tbase - s) : (tbase + s);

        if (s > 0) {
            const unsigned int fa = flagu + (unsigned int)(slot * 32 + lane) * 4u;
            const unsigned int need = (unsigned int)s;
            bool ok;
            do { ok = (ld_acq(fa) >= need); } while (!__all_sync(0xffffffffu, ok));
        }

        float vreg[8];
        unsigned int orv = 0u;
#pragma unroll
        for (int kk = 0; kk < 8; ++kk) {
            vreg[kk] = s_buf[slot][kk * 32 + lane];
            orv |= __float_as_uint(vreg[kk]);
        }

        if (mode == 2) {
            unsigned int o = __reduce_or_sync(0xffffffffu, orv);
            if (lane == 0) s_redu[w] = o;
            __syncthreads();
            if (tid == 0) {
                unsigned int oo = 0u;
                for (int i = 0; i < 16; ++i) oo |= s_redu[i];
                if (oo == 0u) s_dead = 1;
            }
            __syncthreads();
            if (s_dead) { tz = s; break; }
        }

        const unsigned int nbuf  = bufu + (unsigned int)(slot2 * YS + cbase) * 4u;
        const unsigned int tag   = (unsigned int)(s + 1);
        const bool dopush = (mode == 2) || (s + 1 < nsteps);

        if (mode != 2) {
            float4 aA = make_float4(0.f, 0.f, 0.f, 0.f);
            float4 aB = make_float4(0.f, 0.f, 0.f, 0.f);
#pragma unroll
            for (int kk = 0; kk < 8; ++kk) {
                float vv = vreg[kk];
                aA.x = fmaf(vv, aqA[kk].x, aA.x); aA.y = fmaf(vv, aqA[kk].y, aA.y);
                aA.z = fmaf(vv, aqA[kk].z, aA.z); aA.w = fmaf(vv, aqA[kk].w, aA.w);
                aB.x = fmaf(vv, aqB[kk].x, aB.x); aB.y = fmaf(vv, aqB[kk].y, aB.y);
                aB.z = fmaf(vv, aqB[kk].z, aB.z); aB.w = fmaf(vv, aqB[kk].w, aB.w);
            }
#pragma unroll
            for (int off = 16; off > 0; off >>= 1) {
                aA.x += __shfl_xor_sync(0xffffffffu, aA.x, off);
                aA.y += __shfl_xor_sync(0xffffffffu, aA.y, off);
                aA.z += __shfl_xor_sync(0xffffffffu, aA.z, off);
                aA.w += __shfl_xor_sync(0xffffffffu, aA.w, off);
                aB.x += __shfl_xor_sync(0xffffffffu, aB.x, off);
                aB.y += __shfl_xor_sync(0xffffffffu, aB.y, off);
                aB.z += __shfl_xor_sync(0xffffffffu, aB.z, off);
                aB.w += __shfl_xor_sync(0xffffffffu, aB.w, off);
            }
            // carried vector for next step always includes bx[t]
            float4 pA = make_float4(aA.x * bxA.x, aA.y * bxA.y, aA.z * bxA.z, aA.w * bxA.w);
            float4 pB = make_float4(aB.x * bxB.x, aB.y * bxB.y, aB.z * bxB.z, aB.w * bxB.w);

            // output writes (unscaled)
            bool outr = (mode == 0)
                ? (c == 0 ? (s <= 62) : (s >= 31 && s <= 94))
                : (c == CCH - 1 ? (s <= 62) : (s >= 31 && s <= 94));
            if (outr && lane == 2) {
                if (mode == 0) {
                    *(float4*)&out[OFF_ALPHA + t * YS + cbase] = pA;      // alpha = acc*bx
                    *(float4*)&out[OFF_ALPHA + t * YS + cbase + 4] = pB;
                } else {
                    *(float4*)&out[OFF_BETA + t * YS + cbase] = aA;       // raw beta
                    *(float4*)&out[OFF_BETA + t * YS + cbase + 4] = aB;
                }
            }
            if (dopush) {
                if (lane == 0) {
                    push_quad(nbuf, r ^ 1u, pA);
                    push_quad(nbuf + 16u, r ^ 1u, pB);
                    flag_release(flagu + (unsigned int)(slot2 * 32 + 16 + w) * 4u, r ^ 1u, tag);
                } else if (lane == 1) {
                    push_quad(nbuf, r, pA);
                    push_quad(nbuf + 16u, r, pB);
                    flag_release(flagu + (unsigned int)(slot2 * 32 + w) * 4u, r, tag);
                }
            }

            // ---- stitching sums (uniform conditions) ----
            float* dst = 0;
            if (mode == 0) {
                if (c >= 1 && s == 31) dst = &g_SfA[c][r];
                else if ((c == 0 && s == 63) || (c >= 1 && c <= CCH - 2 && s == 95)) dst = &g_SoA[c][r];
                else if (c == CCH - 1 && s == 94) dst = &g_SlA[r];
            } else {
                if (c <= CCH - 2 && s == 31) dst = &g_SfB[c][r];
                else if ((c == CCH - 1 && s == 63) || (c >= 1 && c <= CCH - 2 && s == 95)) dst = &g_SoB[c][r];
            }
            if (dst) {
                float l8 = (mode == 0)
                    ? (pA.x + pA.y + pA.z + pA.w + pB.x + pB.y + pB.z + pB.w)
                    : (aA.x + aA.y + aA.z + aA.w + aB.x + aB.y + aB.z + aB.w);
                if (lane == 0) s_redf[w] = l8;
                __syncthreads();
                if (tid == 0) {
                    float ss = 0.f;
                    for (int i = 0; i < 16; ++i) ss += s_redf[i];
                    *dst = ss;
                }
            }
        } else {
            // ---- exact Viterbi step (bit-identical to R11 semantics) ----
            unsigned int bu[8]; int bi[8];
#pragma unroll
            for (int j = 0; j < 8; ++j) { bu[j] = 0u; bi[j] = lane; }
#pragma unroll
            for (int kk = 0; kk < 8; ++kk) {
                int k = kk * 32 + lane;
                float vv = vreg[kk];
                unsigned int sc[8];
                sc[0] = __float_as_uint(fmul_ftz(vv, aqA[kk].x));
                sc[1] = __float_as_uint(fmul_ftz(vv, aqA[kk].y));
                sc[2] = __float_as_uint(fmul_ftz(vv, aqA[kk].z));
                sc[3] = __float_as_uint(fmul_ftz(vv, aqA[kk].w));
                sc[4] = __float_as_uint(fmul_ftz(vv, aqB[kk].x));
                sc[5] = __float_as_uint(fmul_ftz(vv, aqB[kk].y));
                sc[6] = __float_as_uint(fmul_ftz(vv, aqB[kk].z));
                sc[7] = __float_as_uint(fmul_ftz(vv, aqB[kk].w));
#pragma unroll
                for (int j = 0; j < 8; ++j)
                    if (sc[j] > bu[j]) { bu[j] = sc[j]; bi[j] = k; }
            }
#pragma unroll
            for (int off = 16; off > 0; off >>= 1) {
#pragma unroll
                for (int j = 0; j < 8; ++j) {
                    unsigned int ou = __shfl_xor_sync(0xffffffffu, bu[j], off);
                    int oi = __shfl_xor_sync(0xffffffffu, bi[j], off);
                    if (ou > bu[j] || (ou == bu[j] && oi < bi[j])) { bu[j] = ou; bi[j] = oi; }
                }
            }
            float4 pA, pB;
            pA.x = fmul_ftz(bxA.x, __uint_as_float(bu[0]));
            pA.y = fmul_ftz(bxA.y, __uint_as_float(bu[1]));
            pA.z = fmul_ftz(bxA.z, __uint_as_float(bu[2]));
            pA.w = fmul_ftz(bxA.w, __uint_as_float(bu[3]));
            pB.x = fmul_ftz(bxB.x, __uint_as_float(bu[4]));
            pB.y = fmul_ftz(bxB.y, __uint_as_float(bu[5]));
            pB.z = fmul_ftz(bxB.z, __uint_as_float(bu[6]));
            pB.w = fmul_ftz(bxB.w, __uint_as_float(bu[7]));
            if (lane == 0) {
                push_quad(nbuf, r ^ 1u, pA);
                push_quad(nbuf + 16u, r ^ 1u, pB);
                flag_release(flagu + (unsigned int)(slot2 * 32 + 16 + w) * 4u, r ^ 1u, tag);
            } else if (lane == 1) {
                push_quad(nbuf, r, pA);
                push_quad(nbuf + 16u, r, pB);
                flag_release(flagu + (unsigned int)(slot2 * 32 + w) * 4u, r, tag);
            } else if (lane == 3) {
                uint2 pk;
                pk.x = (unsigned int)bi[0] | ((unsigned int)bi[1] << 8)
                     | ((unsigned int)bi[2] << 16) | ((unsigned int)bi[3] << 24);
                pk.y = (unsigned int)bi[4] | ((unsigned int)bi[5] << 8)
                     | ((unsigned int)bi[6] << 16) | ((unsigned int)bi[7] << 24);
                *(uint2*)(g_bp + (size_t)(t - 1) * YS + cbase) = pk;
            }
        }

        if (s + 1 < nsteps) {
            int tn = (mode == 1) ? (tbase - (s + 1)) : (tbase + (s + 1));
            bxA = __ldg((const float4*)&g_bx[tn * YS + cbase]);
            bxB = __ldg((const float4*)&g_bx[tn * YS + cbase + 4]);
        }
    }

    // ---- Viterbi epilogue ----
    if (mode == 2) {
        if (tz >= 0) {
            unsigned int* bp32 = (unsigned int*)(g_bp + (size_t)tz * YS);
            int n32 = (TM1 - tz) * (YS / 4);
            for (int i = (int)r * 512 + tid; i < n32; i += 1024) bp32[i] = 0u;
        }
        CLUSTER_ARRIVE();
        CLUSTER_WAIT();
        if (r == 0) {
            if (tz >= 0) {
                for (int k = tz + tid; k < TS - 1; k += 512)
                    out[OFF_PATH + k] = 0.0f;
            } else if (w == 0) {
                const int fslot = TM1 % NSLOT;
                const unsigned int fa = flagu + (unsigned int)(fslot * 32 + lane) * 4u;
                bool ok;
                do { ok = (ld_acq(fa) >= (unsigned int)TM1); }
                while (!__all_sync(0xffffffffu, ok));
                if (lane == 0) {
                    unsigned int m = __float_as_uint(s_buf[fslot][0]);
                    int idx = 0;
                    for (int i = 1; i < YS; ++i) {
                        unsigned int vi = __float_as_uint(s_buf[fslot][i]);
                        if (vi > m) { m = vi; idx = i; }
                    }
                    s_last = idx;
                }
            }
            __syncthreads();
            if (tid == 0) {
                int last = s_last;
                out[OFF_PATH + TS - 1] = (float)last;
                int st = last;
                int tstart = (tz >= 0) ? (tz - 1) : (TS - 2);
                for (int tt = tstart; tt >= 0; --tt) {
                    st = (int)g_bp[(size_t)tt * YS + st];
                    out[OFF_PATH + tt] = (float)st;
                }
            }
        }
    }

    CLUSTER_ARRIVE();
    CLUSTER_WAIT();
}

// ---------------------------------------------------------------- stitch
// Serial scalar scan (32 iterations, double) -> per-chunk scales + p.
__global__ void stitch_kernel(float* __restrict__ out) {
    if (threadIdx.x == 0) {
        double k = 1.0;
        g_kap[0] = 1.0f;
        for (int c = 1; c < CCH; ++c) {
            k *= (double)(g_SoA[c - 1][0] + g_SoA[c - 1][1])
               / (double)(g_SfA[c][0] + g_SfA[c][1]);
            g_kap[c] = (float)k;
        }
        double p = k * (double)(g_SlA[0] + g_SlA[1]);
        g_p = (float)p;
        out[OFF_P] = (float)p;
        double l = 1.0;
        g_lam[CCH - 1] = 1.0f;
        for (int c = CCH - 2; c >= 0; --c) {
            l *= (double)(g_SoB[c + 1][0] + g_SoB[c + 1][1])
               / (double)(g_SfB[c][0] + g_SfB[c][1]);
            g_lam[c] = (float)l;
        }
    }
}

// ---------------------------------------------------------------- scale+gamma
__global__ void scale_gamma_kernel(float* __restrict__ out) {
    int t = blockIdx.x, j = threadIdx.x;
    float ka = g_kap[t >> 6], la = g_lam[t >> 6];
    float a = out[OFF_ALPHA + t * YS + j] * ka;
    float b = out[OFF_BETA + t * YS + j] * la;
    out[OFF_ALPHA + t * YS + j] = a;
    out[OFF_BETA + t * YS + j] = b;
    out[OFF_GAMMA + t * YS + j] = a * b / g_p;
}

// ---------------------------------------------------------------- xi
// (R7-proven.) OFF_XI odd -> 4B-aligned region -> scalar STG.32 only.
__global__ void xi_kernel(const float* __restrict__ A, float* __restrict__ out) {
    __shared__ __align__(16) float s_a[YS];
    __shared__ __align__(16) float s_w[YS];
    int t = blockIdx.x, tid = threadIdx.x;
    s_a[tid] = out[OFF_ALPHA + t * YS + tid];
    s_w[tid] = g_bx[(t + 1) * YS + tid] * out[OFF_BETA + (t + 1) * YS + tid];
    __syncthreads();
    float wj = s_w[tid];
    float* ob = out + OFF_XI + (size_t)t * YS * YS + tid;
    const float* Ac = A + tid;
#pragma unroll 8
    for (int i = 0; i < YS; ++i) {
        float ai = s_a[i];
        float av = __ldg(Ac + (size_t)i * YS);
        ob[(size_t)i * YS] = (ai * av) * wj;
    }
}

// ---------------------------------------------------------------- launch
extern "C" void kernel_launch(void* const* d_in, const int* in_sizes, int n_in,
                              void* d_out, int out_size) {
    const int*   x  = (const int*)d_in[0];
    const float* A  = (const float*)d_in[1];
    const float* b  = (const float*)d_in[2];
    const float* pi = (const float*)d_in[3];
    float* out = (float*)d_out;

    prep_bx_kernel<<<TS, YS>>>(x, b);
    chunk_kernel<<<2 * (1 + 2 * CCH), 512>>>(A, pi, out);
    stitch_kernel<<<1, 32>>>(out);
    scale_gamma_kernel<<<TS, YS>>>(out);
    xi_kernel<<<TM1, YS>>>(A, out);
}

// round 13
// speedup vs baseline: 12.2470x; 1.3830x over previous
#include <cuda_runtime.h>

#define YS 256
#define XS 16
#define TS 2048
#define TM1 2047
#define CCH 32       // chunks per recursion (L = 64)
#define NSLOT 3      // ring depth 3
#define WU 15        // warmup steps for interior chunks (lambda2^15 << fp32 eps)

// Output packing (float32):
// alpha (T*Y) | beta (T*Y) | p (1) | gamma (T*Y) | xi ((T-1)*Y*Y) | path (T)
#define OFF_ALPHA 0
#define OFF_BETA  (TS * YS)
#define OFF_P     (2 * TS * YS)
#define OFF_GAMMA (2 * TS * YS + 1)
#define OFF_XI    ((size_t)(3 * TS * YS + 1))
#define OFF_PATH  (OFF_XI + (size_t)TM1 * YS * YS)

// Scratch (static device memory)
__device__ float g_bx[TS * YS];
__device__ unsigned char g_bp[TM1 * YS];
__device__ float g_SfA[CCH][2], g_SoA[CCH][2];   // alpha first/overlap sums per (chunk, ctarank)
__device__ float g_SfB[CCH][2], g_SoB[CCH][2];   // beta
__device__ float g_SlA[2];                       // sum alpha(T-1) raw
__device__ float g_kap[CCH], g_lam[CCH];
__device__ float g_p;

// FTZ multiply — matches reference flush-to-zero f32 (bit-verified R6).
__device__ __forceinline__ float fmul_ftz(float a, float b) {
    float r;
    asm("mul.rn.ftz.f32 %0, %1, %2;" : "=f"(r) : "f"(a), "f"(b));
    return r;
}
__device__ __forceinline__ unsigned int smem_u32(const void* p) {
    unsigned int a;
    asm("{ .reg .u64 t; cvta.to.shared.u64 t, %1; cvt.u32.u64 %0, t; }"
        : "=r"(a) : "l"(p));
    return a;
}
__device__ __forceinline__ unsigned int ctarank() {
    unsigned int r;
    asm("mov.u32 %0, %%cluster_ctarank;" : "=r"(r));
    return r;
}
__device__ __forceinline__ void push_quad(unsigned int bufaddr, unsigned int rank,
                                          float4 v) {
    asm volatile(
        "{ .reg .b32 ra;\n\t"
        "mapa.shared::cluster.u32 ra, %0, %1;\n\t"
        "st.shared::cluster.v4.f32 [ra], {%2,%3,%4,%5}; }"
        :: "r"(bufaddr), "r"(rank),
           "f"(v.x), "f"(v.y), "f"(v.z), "f"(v.w) : "memory");
}
__device__ __forceinline__ void flag_release(unsigned int flagaddr, unsigned int rank,
                                             unsigned int val) {
    asm volatile(
        "{ .reg .b32 rb;\n\t"
        "mapa.shared::cluster.u32 rb, %0, %1;\n\t"
        "st.release.cluster.shared::cluster.b32 [rb], %2; }"
        :: "r"(flagaddr), "r"(rank), "r"(val) : "memory");
}
__device__ __forceinline__ unsigned int ld_acq(unsigned int addr) {
    unsigned int v;
    asm volatile("ld.acquire.cluster.shared::cta.b32 %0, [%1];"
                 : "=r"(v) : "r"(addr) : "memory");
    return v;
}
#define CLUSTER_ARRIVE() asm volatile("barrier.cluster.arrive.aligned;" ::: "memory")
#define CLUSTER_WAIT()   asm volatile("barrier.cluster.wait.aligned;" ::: "memory")

// ---------------------------------------------------------------- prep
__global__ void prep_bx_kernel(const int* __restrict__ x,
                               const float* __restrict__ b) {
    int t = blockIdx.x, j = threadIdx.x;
    g_bx[t * YS + j] = b[j * XS + x[t]];
}

// ---------------------------------------------------------------- chunk kernel
// grid = 130 CTAs = 65 clusters of 2, 512 threads. (R12-proven structure;
// only the warmup length changed 31 -> WU=15.)
// pair 0: exact serial Viterbi. pairs 1..32: alpha chunk. pairs 33..64: beta.
__global__ void __cluster_dims__(2, 1, 1) __launch_bounds__(512, 1)
chunk_kernel(const float* __restrict__ A,
             const float* __restrict__ pi,
             float* __restrict__ out) {
    __shared__ __align__(16) float s_buf[NSLOT][YS];
    __shared__ __align__(16) unsigned int s_flags[NSLOT][32];
    __shared__ float s_redf[16];
    __shared__ unsigned int s_redu[16];
    __shared__ int s_dead, s_last;

    const int tid  = threadIdx.x;
    const int w    = tid >> 5;           // 0..15
    const int lane = tid & 31;
    const unsigned int r = ctarank();
    const int pair = blockIdx.x >> 1;
    const int mode = (pair == 0) ? 2 : (pair <= CCH ? 0 : 1);
    const int c    = (pair == 0) ? 0 : (pair <= CCH ? pair - 1 : pair - 1 - CCH);
    const int cbase = (int)r * 128 + w * 8;      // this warp's 8 output columns

    const unsigned int bufu  = smem_u32(&s_buf[0][0]);
    const unsigned int flagu = smem_u32(&s_flags[0][0]);

    if (tid < NSLOT * 32) ((unsigned int*)s_flags)[tid] = 0u;
    if (tid == 0) { s_dead = 0; s_last = 0; }

    // ---- A half into registers: k = kk*32+lane pairs with v[k] ----
    float4 aqA[8], aqB[8];
    if (mode != 1) {
#pragma unroll
        for (int kk = 0; kk < 8; ++kk) {
            aqA[kk] = __ldg((const float4*)(A + (size_t)(kk * 32 + lane) * YS + cbase));
            aqB[kk] = __ldg((const float4*)(A + (size_t)(kk * 32 + lane) * YS + cbase + 4));
        }
    } else {
#pragma unroll
        for (int kk = 0; kk < 8; ++kk) {
            int k = kk * 32 + lane;
            aqA[kk].x = __ldg(A + (size_t)(cbase + 0) * YS + k);
            aqA[kk].y = __ldg(A + (size_t)(cbase + 1) * YS + k);
            aqA[kk].z = __ldg(A + (size_t)(cbase + 2) * YS + k);
            aqA[kk].w = __ldg(A + (size_t)(cbase + 3) * YS + k);
            aqB[kk].x = __ldg(A + (size_t)(cbase + 4) * YS + k);
            aqB[kk].y = __ldg(A + (size_t)(cbase + 5) * YS + k);
            aqB[kk].z = __ldg(A + (size_t)(cbase + 6) * YS + k);
            aqB[kk].w = __ldg(A + (size_t)(cbase + 7) * YS + k);
        }
    }

    // ---- step count and t-mapping (W = WU warmup for interior chunks) ----
    int nsteps, tbase;  // mode0/2: t = tbase + s ; mode1: t = tbase - s
    if (mode == 0) {
        nsteps = (c == 0) ? 64 : (c == CCH - 1 ? (64 + WU) : (64 + WU + 1));
        tbase  = (c == 0) ? 1 : (64 * c - WU);
    } else if (mode == 1) {
        nsteps = (c == CCH - 1) ? 64 : (c == 0 ? (64 + WU) : (64 + WU + 1));
        tbase  = (c == CCH - 1) ? 2046 : (64 * c + 63 + WU);
    } else {
        nsteps = TM1;
        tbase  = 1;
    }

    // ---- initial vector (slot 0) + exact boundary writes ----
    if (tid < YS) {
        float v;
        if (mode == 0) {
            v = (c == 0) ? g_bx[tid] * pi[tid] : 1.0f;
            if (c == 0 && r == 0) out[OFF_ALPHA + tid] = v;
        } else if (mode == 1) {
            if (c == CCH - 1) {
                v = g_bx[(TS - 1) * YS + tid];
                if (r == 0) out[OFF_BETA + (TS - 1) * YS + tid] = 1.0f;
            } else v = 1.0f;
        } else {
            v = g_bx[tid] * pi[tid];
        }
        s_buf[0][tid] = v;
    }
    __syncthreads();
    CLUSTER_ARRIVE();
    CLUSTER_WAIT();

    int tz = -1;
    int t = tbase;
    float4 bxA = __ldg((const float4*)&g_bx[t * YS + cbase]);
    float4 bxB = __ldg((const float4*)&g_bx[t * YS + cbase + 4]);

    for (int s = 0; s < nsteps; ++s) {
        const int slot  = s % NSLOT;
        const int slot2 = (s + 1) % NSLOT;
        t = (mode == 1) ? (tbase - s) : (tbase + s);

        if (s > 0) {
            const unsigned int fa = flagu + (unsigned int)(slot * 32 + lane) * 4u;
            const unsigned int need = (unsigned int)s;
            bool ok;
            do { ok = (ld_acq(fa) >= need); } while (!__all_sync(0xffffffffu, ok));
        }

        float vreg[8];
        unsigned int orv = 0u;
#pragma unroll
        for (int kk = 0; kk < 8; ++kk) {
            vreg[kk] = s_buf[slot][kk * 32 + lane];
            orv |= __float_as_uint(vreg[kk]);
        }

        if (mode == 2) {
            unsigned int o = __reduce_or_sync(0xffffffffu, orv);
            if (lane == 0) s_redu[w] = o;
            __syncthreads();
            if (tid == 0) {
                unsigned int oo = 0u;
                for (int i = 0; i < 16; ++i) oo |= s_redu[i];
                if (oo == 0u) s_dead = 1;
            }
            __syncthreads();
            if (s_dead) { tz = s; break; }
        }

        const unsigned int nbuf  = bufu + (unsigned int)(slot2 * YS + cbase) * 4u;
        const unsigned int tag   = (unsigned int)(s + 1);
        const bool dopush = (mode == 2) || (s + 1 < nsteps);

        if (mode != 2) {
            float4 aA = make_float4(0.f, 0.f, 0.f, 0.f);
            float4 aB = make_float4(0.f, 0.f, 0.f, 0.f);
#pragma unroll
            for (int kk = 0; kk < 8; ++kk) {
                float vv = vreg[kk];
                aA.x = fmaf(vv, aqA[kk].x, aA.x); aA.y = fmaf(vv, aqA[kk].y, aA.y);
                aA.z = fmaf(vv, aqA[kk].z, aA.z); aA.w = fmaf(vv, aqA[kk].w, aA.w);
                aB.x = fmaf(vv, aqB[kk].x, aB.x); aB.y = fmaf(vv, aqB[kk].y, aB.y);
                aB.z = fmaf(vv, aqB[kk].z, aB.z); aB.w = fmaf(vv, aqB[kk].w, aB.w);
            }
#pragma unroll
            for (int off = 16; off > 0; off >>= 1) {
                aA.x += __shfl_xor_sync(0xffffffffu, aA.x, off);
                aA.y += __shfl_xor_sync(0xffffffffu, aA.y, off);
                aA.z += __shfl_xor_sync(0xffffffffu, aA.z, off);
                aA.w += __shfl_xor_sync(0xffffffffu, aA.w, off);
                aB.x += __shfl_xor_sync(0xffffffffu, aB.x, off);
                aB.y += __shfl_xor_sync(0xffffffffu, aB.y, off);
                aB.z += __shfl_xor_sync(0xffffffffu, aB.z, off);
                aB.w += __shfl_xor_sync(0xffffffffu, aB.w, off);
            }
            float4 pA = make_float4(aA.x * bxA.x, aA.y * bxA.y, aA.z * bxA.z, aA.w * bxA.w);
            float4 pB = make_float4(aB.x * bxB.x, aB.y * bxB.y, aB.z * bxB.z, aB.w * bxB.w);

            // output writes (unscaled); window for W=WU
            bool outr = (mode == 0)
                ? (c == 0 ? (s <= 62) : (s >= WU && s <= WU + 63))
                : (c == CCH - 1 ? (s <= 62) : (s >= WU && s <= WU + 63));
            if (outr && lane == 2) {
                if (mode == 0) {
                    *(float4*)&out[OFF_ALPHA + t * YS + cbase] = pA;
                    *(float4*)&out[OFF_ALPHA + t * YS + cbase + 4] = pB;
                } else {
                    *(float4*)&out[OFF_BETA + t * YS + cbase] = aA;
                    *(float4*)&out[OFF_BETA + t * YS + cbase + 4] = aB;
                }
            }
            if (dopush) {
                if (lane == 0) {
                    push_quad(nbuf, r ^ 1u, pA);
                    push_quad(nbuf + 16u, r ^ 1u, pB);
                    flag_release(flagu + (unsigned int)(slot2 * 32 + 16 + w) * 4u, r ^ 1u, tag);
                } else if (lane == 1) {
                    push_quad(nbuf, r, pA);
                    push_quad(nbuf + 16u, r, pB);
                    flag_release(flagu + (unsigned int)(slot2 * 32 + w) * 4u, r, tag);
                }
            }

            // ---- stitching sums (uniform conditions; W=WU indices) ----
            float* dst = 0;
            if (mode == 0) {
                if (c >= 1 && s == WU) dst = &g_SfA[c][r];
                else if ((c == 0 && s == 63) || (c >= 1 && c <= CCH - 2 && s == WU + 64)) dst = &g_SoA[c][r];
                else if (c == CCH - 1 && s == WU + 63) dst = &g_SlA[r];
            } else {
                if (c <= CCH - 2 && s == WU) dst = &g_SfB[c][r];
                else if ((c == CCH - 1 && s == 63) || (c >= 1 && c <= CCH - 2 && s == WU + 64)) dst = &g_SoB[c][r];
            }
            if (dst) {
                float l8 = (mode == 0)
                    ? (pA.x + pA.y + pA.z + pA.w + pB.x + pB.y + pB.z + pB.w)
                    : (aA.x + aA.y + aA.z + aA.w + aB.x + aB.y + aB.z + aB.w);
                if (lane == 0) s_redf[w] = l8;
                __syncthreads();
                if (tid == 0) {
                    float ss = 0.f;
                    for (int i = 0; i < 16; ++i) ss += s_redf[i];
                    *dst = ss;
                }
            }
        } else {
            // ---- exact Viterbi step (bit-identical semantics) ----
            unsigned int bu[8]; int bi[8];
#pragma unroll
            for (int j = 0; j < 8; ++j) { bu[j] = 0u; bi[j] = lane; }
#pragma unroll
            for (int kk = 0; kk < 8; ++kk) {
                int k = kk * 32 + lane;
                float vv = vreg[kk];
                unsigned int sc[8];
                sc[0] = __float_as_uint(fmul_ftz(vv, aqA[kk].x));
                sc[1] = __float_as_uint(fmul_ftz(vv, aqA[kk].y));
                sc[2] = __float_as_uint(fmul_ftz(vv, aqA[kk].z));
                sc[3] = __float_as_uint(fmul_ftz(vv, aqA[kk].w));
                sc[4] = __float_as_uint(fmul_ftz(vv, aqB[kk].x));
                sc[5] = __float_as_uint(fmul_ftz(vv, aqB[kk].y));
                sc[6] = __float_as_uint(fmul_ftz(vv, aqB[kk].z));
                sc[7] = __float_as_uint(fmul_ftz(vv, aqB[kk].w));
#pragma unroll
                for (int j = 0; j < 8; ++j)
                    if (sc[j] > bu[j]) { bu[j] = sc[j]; bi[j] = k; }
            }
#pragma unroll
            for (int off = 16; off > 0; off >>= 1) {
#pragma unroll
                for (int j = 0; j < 8; ++j) {
                    unsigned int ou = __shfl_xor_sync(0xffffffffu, bu[j], off);
                    int oi = __shfl_xor_sync(0xffffffffu, bi[j], off);
                    if (ou > bu[j] || (ou == bu[j] && oi < bi[j])) { bu[j] = ou; bi[j] = oi; }
                }
            }
            float4 pA, pB;
            pA.x = fmul_ftz(bxA.x, __uint_as_float(bu[0]));
            pA.y = fmul_ftz(bxA.y, __uint_as_float(bu[1]));
            pA.z = fmul_ftz(bxA.z, __uint_as_float(bu[2]));
            pA.w = fmul_ftz(bxA.w, __uint_as_float(bu[3]));
            pB.x = fmul_ftz(bxB.x, __uint_as_float(bu[4]));
            pB.y = fmul_ftz(bxB.y, __uint_as_float(bu[5]));
            pB.z = fmul_ftz(bxB.z, __uint_as_float(bu[6]));
            pB.w = fmul_ftz(bxB.w, __uint_as_float(bu[7]));
            if (lane == 0) {
                push_quad(nbuf, r ^ 1u, pA);
                push_quad(nbuf + 16u, r ^ 1u, pB);
                flag_release(flagu + (unsigned int)(slot2 * 32 + 16 + w) * 4u, r ^ 1u, tag);
            } else if (lane == 1) {
                push_quad(nbuf, r, pA);
                push_quad(nbuf + 16u, r, pB);
                flag_release(flagu + (unsigned int)(slot2 * 32 + w) * 4u, r, tag);
            } else if (lane == 3) {
                uint2 pk;
                pk.x = (unsigned int)bi[0] | ((unsigned int)bi[1] << 8)
                     | ((unsigned int)bi[2] << 16) | ((unsigned int)bi[3] << 24);
                pk.y = (unsigned int)bi[4] | ((unsigned int)bi[5] << 8)
                     | ((unsigned int)bi[6] << 16) | ((unsigned int)bi[7] << 24);
                *(uint2*)(g_bp + (size_t)(t - 1) * YS + cbase) = pk;
            }
        }

        if (s + 1 < nsteps) {
            int tn = (mode == 1) ? (tbase - (s + 1)) : (tbase + (s + 1));
            bxA = __ldg((const float4*)&g_bx[tn * YS + cbase]);
            bxB = __ldg((const float4*)&g_bx[tn * YS + cbase + 4]);
        }
    }

    // ---- Viterbi epilogue ----
    if (mode == 2) {
        if (tz >= 0) {
            unsigned int* bp32 = (unsigned int*)(g_bp + (size_t)tz * YS);
            int n32 = (TM1 - tz) * (YS / 4);
            for (int i = (int)r * 512 + tid; i < n32; i += 1024) bp32[i] = 0u;
        }
        CLUSTER_ARRIVE();
        CLUSTER_WAIT();
        if (r == 0) {
            if (tz >= 0) {
                for (int k = tz + tid; k < TS - 1; k += 512)
                    out[OFF_PATH + k] = 0.0f;
            } else if (w == 0) {
                const int fslot = TM1 % NSLOT;
                const unsigned int fa = flagu + (unsigned int)(fslot * 32 + lane) * 4u;
                bool ok;
                do { ok = (ld_acq(fa) >= (unsigned int)TM1); }
                while (!__all_sync(0xffffffffu, ok));
                if (lane == 0) {
                    unsigned int m = __float_as_uint(s_buf[fslot][0]);
                    int idx = 0;
                    for (int i = 1; i < YS; ++i) {
                        unsigned int vi = __float_as_uint(s_buf[fslot][i]);
                        if (vi > m) { m = vi; idx = i; }
                    }
                    s_last = idx;
                }
            }
            __syncthreads();
            if (tid == 0) {
                int last = s_last;
                out[OFF_PATH + TS - 1] = (float)last;
                int st = last;
                int tstart = (tz >= 0) ? (tz - 1) : (TS - 2);
                for (int tt = tstart; tt >= 0; --tt) {
                    st = (int)g_bp[(size_t)tt * YS + st];
                    out[OFF_PATH + tt] = (float)st;
                }
            }
        }
    }

    CLUSTER_ARRIVE();
    CLUSTER_WAIT();
}

// ---------------------------------------------------------------- stitch
// Parallel-stage the 128 partial sums, then two independent 32-long scans on
// two threads in different warps (removes the serial dependent-load chain).
__global__ void stitch_kernel(float* __restrict__ out) {
    __shared__ float sSoA[CCH], sSfA[CCH], sSoB[CCH], sSfB[CCH];
    int tid = threadIdx.x;  // 64 threads
    if (tid < CCH) {
        sSoA[tid] = g_SoA[tid][0] + g_SoA[tid][1];
        sSfA[tid] = g_SfA[tid][0] + g_SfA[tid][1];
    } else {
        int c = tid - CCH;
        sSoB[c] = g_SoB[c][0] + g_SoB[c][1];
        sSfB[c] = g_SfB[c][0] + g_SfB[c][1];
    }
    __syncthreads();
    if (tid == 0) {
        double k = 1.0;
        g_kap[0] = 1.0f;
        for (int c = 1; c < CCH; ++c) {
            k *= (double)sSoA[c - 1] / (double)sSfA[c];
            g_kap[c] = (float)k;
        }
        double p = k * (double)(g_SlA[0] + g_SlA[1]);
        g_p = (float)p;
        out[OFF_P] = (float)p;
    }
    if (tid == 32) {
        double l = 1.0;
        g_lam[CCH - 1] = 1.0f;
        for (int c = CCH - 2; c >= 0; --c) {
            l *= (double)sSoB[c + 1] / (double)sSfB[c];
            g_lam[c] = (float)l;
        }
    }
}

// ---------------------------------------------------------------- scale+gamma
__global__ void scale_gamma_kernel(float* __restrict__ out) {
    int t = blockIdx.x, j = threadIdx.x;
    float ka = g_kap[t >> 6], la = g_lam[t >> 6];
    float a = out[OFF_ALPHA + t * YS + j] * ka;
    float b = out[OFF_BETA + t * YS + j] * la;
    out[OFF_ALPHA + t * YS + j] = a;
    out[OFF_BETA + t * YS + j] = b;
    out[OFF_GAMMA + t * YS + j] = a * b / g_p;
}

// ---------------------------------------------------------------- xi
// OFF_XI is odd, but (OFF_XI + 3) % 4 == 0: within each 256-word row, quads at
// word offset 3+4q (q=0..62) are 16B-aligned in GMEM. Stage 8 rows through
// SMEM (compute column-per-thread as before), then emit 63 STG.128 + 4 scalar
// stores per row: 4x fewer store instructions than all-scalar.
#define XG 8
__global__ void xi_kernel(const float* __restrict__ A, float* __restrict__ out) {
    __shared__ __align__(16) float s_a[YS];
    __shared__ __align__(16) float s_w[YS];
    __shared__ __align__(16) float s_x[XG][264];   // +1 word shift -> smem quads aligned
    int t = blockIdx.x, tid = threadIdx.x;
    s_a[tid] = out[OFF_ALPHA + t * YS + tid];
    s_w[tid] = g_bx[(t + 1) * YS + tid] * out[OFF_BETA + (t + 1) * YS + tid];
    __syncthreads();

    float wj = s_w[tid];
    const float* Ac = A + tid;
    float* base = out + OFF_XI + (size_t)t * YS * YS;

    for (int g0 = 0; g0 < YS; g0 += XG) {
        // compute 8 rows into staging (coalesced A loads, stride-1 STS)
#pragma unroll
        for (int q = 0; q < XG; ++q) {
            int i = g0 + q;
            float av = __ldg(Ac + (size_t)i * YS);
            s_x[q][tid + 1] = (s_a[i] * av) * wj;
        }
        __syncthreads();
        // vector stores: u in [0, XG*63) -> row u/63, quad u%63
#pragma unroll 2
        for (int u = tid; u < XG * 63; u += YS) {
            int row = u / 63, q = u - row * 63;
            float4 v = *(const float4*)&s_x[row][4 + 4 * q];
            *(float4*)(base + (size_t)(g0 + row) * YS + 3 + 4 * q) = v;
        }
        // head (0,1,2) + tail (255) scalars
        if (tid < XG * 4) {
            int row = tid >> 2, cc = tid & 3;
            int col = (cc < 3) ? cc : 255;
            base[(size_t)(g0 + row) * YS + col] = s_x[row][col + 1];
        }
        __syncthreads();
    }
}

// ---------------------------------------------------------------- launch
extern "C" void kernel_launch(void* const* d_in, const int* in_sizes, int n_in,
                              void* d_out, int out_size) {
    const int*   x  = (const int*)d_in[0];
    const float* A  = (const float*)d_in[1];
    const float* b  = (const float*)d_in[2];
    const float* pi = (const float*)d_in[3];
    float* out = (float*)d_out;

    prep_bx_kernel<<<TS, YS>>>(x, b);
    chunk_kernel<<<2 * (1 + 2 * CCH), 512>>>(A, pi, out);
    stitch_kernel<<<1, 64>>>(out);
    scale_gamma_kernel<<<TS, YS>>>(out);
    xi_kernel<<<TM1, YS>>>(A, out);
}

// round 14
// speedup vs baseline: 12.3292x; 1.0067x over previous
#include <cuda_runtime.h>

#define YS 256
#define XS 16
#define TS 2048
#define TM1 2047
#define CCH 32       // chunks per recursion (L = 64)
#define NSLOT 3      // ring depth 3
#define WU 15        // warmup steps for interior chunks

// Output packing (float32):
// alpha (T*Y) | beta (T*Y) | p (1) | gamma (T*Y) | xi ((T-1)*Y*Y) | path (T)
#define OFF_ALPHA 0
#define OFF_BETA  (TS * YS)
#define OFF_P     (2 * TS * YS)
#define OFF_GAMMA (2 * TS * YS + 1)
#define OFF_XI    ((size_t)(3 * TS * YS + 1))
#define OFF_PATH  (OFF_XI + (size_t)TM1 * YS * YS)

// Scratch (static device memory)
__device__ float g_bx[TS * YS];
__device__ float g_alpha[TS * YS];       // raw (unscaled) alpha
__device__ float g_beta[TS * YS];        // raw (unscaled) beta
__device__ unsigned char g_bp[TM1 * YS];
__device__ float g_SfA[CCH][2], g_SoA[CCH][2];
__device__ float g_SfB[CCH][2], g_SoB[CCH][2];
__device__ float g_SlA[2];
__device__ float g_kap[CCH], g_lam[CCH];
__device__ float g_p;

// FTZ multiply — matches reference flush-to-zero f32 (bit-verified R6).
__device__ __forceinline__ float fmul_ftz(float a, float b) {
    float r;
    asm("mul.rn.ftz.f32 %0, %1, %2;" : "=f"(r) : "f"(a), "f"(b));
    return r;
}
__device__ __forceinline__ unsigned int smem_u32(const void* p) {
    unsigned int a;
    asm("{ .reg .u64 t; cvta.to.shared.u64 t, %1; cvt.u32.u64 %0, t; }"
        : "=r"(a) : "l"(p));
    return a;
}
__device__ __forceinline__ unsigned int ctarank() {
    unsigned int r;
    asm("mov.u32 %0, %%cluster_ctarank;" : "=r"(r));
    return r;
}
__device__ __forceinline__ void push_quad(unsigned int bufaddr, unsigned int rank,
                                          float4 v) {
    asm volatile(
        "{ .reg .b32 ra;\n\t"
        "mapa.shared::cluster.u32 ra, %0, %1;\n\t"
        "st.shared::cluster.v4.f32 [ra], {%2,%3,%4,%5}; }"
        :: "r"(bufaddr), "r"(rank),
           "f"(v.x), "f"(v.y), "f"(v.z), "f"(v.w) : "memory");
}
__device__ __forceinline__ void push_u64(unsigned int addr, unsigned int rank,
                                         unsigned long long v) {
    asm volatile(
        "{ .reg .b32 ra;\n\t"
        "mapa.shared::cluster.u32 ra, %0, %1;\n\t"
        "st.shared::cluster.b64 [ra], %2; }"
        :: "r"(addr), "r"(rank), "l"(v) : "memory");
}
__device__ __forceinline__ void flag_release(unsigned int flagaddr, unsigned int rank,
                                             unsigned int val) {
    asm volatile(
        "{ .reg .b32 rb;\n\t"
        "mapa.shared::cluster.u32 rb, %0, %1;\n\t"
        "st.release.cluster.shared::cluster.b32 [rb], %2; }"
        :: "r"(flagaddr), "r"(rank), "r"(val) : "memory");
}
__device__ __forceinline__ unsigned int ld_rlx(unsigned int addr) {
    unsigned int v;
    asm volatile("ld.relaxed.cluster.shared::cta.b32 %0, [%1];"
                 : "=r"(v) : "r"(addr) : "memory");
    return v;
}
__device__ __forceinline__ unsigned int ld_acq(unsigned int addr) {
    unsigned int v;
    asm volatile("ld.acquire.cluster.shared::cta.b32 %0, [%1];"
                 : "=r"(v) : "r"(addr) : "memory");
    return v;
}
#define CLUSTER_ARRIVE() asm volatile("barrier.cluster.arrive.aligned;" ::: "memory")
#define CLUSTER_WAIT()   asm volatile("barrier.cluster.wait.aligned;" ::: "memory")

// ---------------------------------------------------------------- prep
__global__ void prep_bx_kernel(const int* __restrict__ x,
                               const float* __restrict__ b) {
    int t = blockIdx.x, j = threadIdx.x;
    g_bx[t * YS + j] = b[j * XS + x[t]];
}

// dummy launches: position chunk_kernel as the 4th launch for ncu capture
__global__ void dummy_kernel() {}

// ---------------------------------------------------------------- chunk kernel
// grid = 130 CTAs = 65 clusters of 2, 512 threads. (R13-proven structure.)
// pair 0: exact serial Viterbi. pairs 1..32: alpha chunk. pairs 33..64: beta.
// Raw alpha/beta go to g_alpha/g_beta scratch; scaling fused into xi kernel.
__global__ void __cluster_dims__(2, 1, 1) __launch_bounds__(512, 1)
chunk_kernel(const float* __restrict__ A,
             const float* __restrict__ pi,
             float* __restrict__ out) {
    __shared__ __align__(16) float s_buf[NSLOT][YS];
    __shared__ __align__(16) unsigned int s_flags[NSLOT][32];
    __shared__ __align__(8) unsigned char s_bpc[64 * YS];   // Viterbi bp cache (rank 0)
    __shared__ float s_redf[16];
    __shared__ unsigned int s_redu[16];
    __shared__ int s_dead, s_last;

    const int tid  = threadIdx.x;
    const int w    = tid >> 5;
    const int lane = tid & 31;
    const unsigned int r = ctarank();
    const int pair = blockIdx.x >> 1;
    const int mode = (pair == 0) ? 2 : (pair <= CCH ? 0 : 1);
    const int c    = (pair == 0) ? 0 : (pair <= CCH ? pair - 1 : pair - 1 - CCH);
    const int cbase = (int)r * 128 + w * 8;

    const unsigned int bufu  = smem_u32(&s_buf[0][0]);
    const unsigned int flagu = smem_u32(&s_flags[0][0]);
    const unsigned int bpcu  = smem_u32(&s_bpc[0]);

    if (tid < NSLOT * 32) ((unsigned int*)s_flags)[tid] = 0u;
    if (tid == 0) { s_dead = 0; s_last = 0; }

    // ---- A half into registers ----
    float4 aqA[8], aqB[8];
    if (mode != 1) {
#pragma unroll
        for (int kk = 0; kk < 8; ++kk) {
            aqA[kk] = __ldg((const float4*)(A + (size_t)(kk * 32 + lane) * YS + cbase));
            aqB[kk] = __ldg((const float4*)(A + (size_t)(kk * 32 + lane) * YS + cbase + 4));
        }
    } else {
#pragma unroll
        for (int kk = 0; kk < 8; ++kk) {
            int k = kk * 32 + lane;
            aqA[kk].x = __ldg(A + (size_t)(cbase + 0) * YS + k);
            aqA[kk].y = __ldg(A + (size_t)(cbase + 1) * YS + k);
            aqA[kk].z = __ldg(A + (size_t)(cbase + 2) * YS + k);
            aqA[kk].w = __ldg(A + (size_t)(cbase + 3) * YS + k);
            aqB[kk].x = __ldg(A + (size_t)(cbase + 4) * YS + k);
            aqB[kk].y = __ldg(A + (size_t)(cbase + 5) * YS + k);
            aqB[kk].z = __ldg(A + (size_t)(cbase + 6) * YS + k);
            aqB[kk].w = __ldg(A + (size_t)(cbase + 7) * YS + k);
        }
    }

    // ---- step count and t-mapping ----
    int nsteps, tbase;
    if (mode == 0) {
        nsteps = (c == 0) ? 64 : (c == CCH - 1 ? (64 + WU) : (64 + WU + 1));
        tbase  = (c == 0) ? 1 : (64 * c - WU);
    } else if (mode == 1) {
        nsteps = (c == CCH - 1) ? 64 : (c == 0 ? (64 + WU) : (64 + WU + 1));
        tbase  = (c == CCH - 1) ? 2046 : (64 * c + 63 + WU);
    } else {
        nsteps = TM1;
        tbase  = 1;
    }

    // ---- initial vector + exact boundary writes (raw, to scratch) ----
    if (tid < YS) {
        float v;
        if (mode == 0) {
            v = (c == 0) ? g_bx[tid] * pi[tid] : 1.0f;
            if (c == 0 && r == 0) g_alpha[tid] = v;
        } else if (mode == 1) {
            if (c == CCH - 1) {
                v = g_bx[(TS - 1) * YS + tid];
                if (r == 0) g_beta[(TS - 1) * YS + tid] = 1.0f;
            } else v = 1.0f;
        } else {
            v = g_bx[tid] * pi[tid];
        }
        s_buf[0][tid] = v;
    }
    __syncthreads();
    CLUSTER_ARRIVE();
    CLUSTER_WAIT();

    int tz = -1;
    int t = tbase;
    float4 bxA = __ldg((const float4*)&g_bx[t * YS + cbase]);
    float4 bxB = __ldg((const float4*)&g_bx[t * YS + cbase + 4]);

    for (int s = 0; s < nsteps; ++s) {
        const int slot  = s % NSLOT;
        const int slot2 = (s + 1) % NSLOT;
        t = (mode == 1) ? (tbase - s) : (tbase + s);

        if (s > 0) {
            const unsigned int fa = flagu + (unsigned int)(slot * 32 + lane) * 4u;
            const unsigned int need = (unsigned int)s;
            bool ok;
            do { ok = (ld_rlx(fa) >= need); } while (!__all_sync(0xffffffffu, ok));
            ld_acq(fa);   // single acquire establishes sync (relaxed poll above)
        }

        float vreg[8];
        unsigned int orv = 0u;
#pragma unroll
        for (int kk = 0; kk < 8; ++kk) {
            vreg[kk] = s_buf[slot][kk * 32 + lane];
            orv |= __float_as_uint(vreg[kk]);
        }

        if (mode == 2) {
            unsigned int o = __reduce_or_sync(0xffffffffu, orv);
            if (lane == 0) s_redu[w] = o;
            __syncthreads();
            if (tid == 0) {
                unsigned int oo = 0u;
                for (int i = 0; i < 16; ++i) oo |= s_redu[i];
                if (oo == 0u) s_dead = 1;
            }
            __syncthreads();
            if (s_dead) { tz = s; break; }
        }

        const unsigned int nbuf  = bufu + (unsigned int)(slot2 * YS + cbase) * 4u;
        const unsigned int tag   = (unsigned int)(s + 1);
        const bool dopush = (mode == 2) || (s + 1 < nsteps);

        if (mode != 2) {
            float4 aA = make_float4(0.f, 0.f, 0.f, 0.f);
            float4 aB = make_float4(0.f, 0.f, 0.f, 0.f);
#pragma unroll
            for (int kk = 0; kk < 8; ++kk) {
                float vv = vreg[kk];
                aA.x = fmaf(vv, aqA[kk].x, aA.x); aA.y = fmaf(vv, aqA[kk].y, aA.y);
                aA.z = fmaf(vv, aqA[kk].z, aA.z); aA.w = fmaf(vv, aqA[kk].w, aA.w);
                aB.x = fmaf(vv, aqB[kk].x, aB.x); aB.y = fmaf(vv, aqB[kk].y, aB.y);
                aB.z = fmaf(vv, aqB[kk].z, aB.z); aB.w = fmaf(vv, aqB[kk].w, aB.w);
            }
#pragma unroll
            for (int off = 16; off > 0; off >>= 1) {
                aA.x += __shfl_xor_sync(0xffffffffu, aA.x, off);
                aA.y += __shfl_xor_sync(0xffffffffu, aA.y, off);
                aA.z += __shfl_xor_sync(0xffffffffu, aA.z, off);
                aA.w += __shfl_xor_sync(0xffffffffu, aA.w, off);
                aB.x += __shfl_xor_sync(0xffffffffu, aB.x, off);
                aB.y += __shfl_xor_sync(0xffffffffu, aB.y, off);
                aB.z += __shfl_xor_sync(0xffffffffu, aB.z, off);
                aB.w += __shfl_xor_sync(0xffffffffu, aB.w, off);
            }
            float4 pA = make_float4(aA.x * bxA.x, aA.y * bxA.y, aA.z * bxA.z, aA.w * bxA.w);
            float4 pB = make_float4(aB.x * bxB.x, aB.y * bxB.y, aB.z * bxB.z, aB.w * bxB.w);

            bool outr = (mode == 0)
                ? (c == 0 ? (s <= 62) : (s >= WU && s <= WU + 63))
                : (c == CCH - 1 ? (s <= 62) : (s >= WU && s <= WU + 63));
            if (outr && lane == 2) {
                if (mode == 0) {
                    *(float4*)&g_alpha[t * YS + cbase] = pA;
                    *(float4*)&g_alpha[t * YS + cbase + 4] = pB;
                } else {
                    *(float4*)&g_beta[t * YS + cbase] = aA;
                    *(float4*)&g_beta[t * YS + cbase + 4] = aB;
                }
            }
            if (dopush) {
                if (lane == 0) {
                    push_quad(nbuf, r ^ 1u, pA);
                    push_quad(nbuf + 16u, r ^ 1u, pB);
                    flag_release(flagu + (unsigned int)(slot2 * 32 + 16 + w) * 4u, r ^ 1u, tag);
                } else if (lane == 1) {
                    push_quad(nbuf, r, pA);
                    push_quad(nbuf + 16u, r, pB);
                    flag_release(flagu + (unsigned int)(slot2 * 32 + w) * 4u, r, tag);
                }
            }

            // ---- stitching sums ----
            float* dst = 0;
            if (mode == 0) {
                if (c >= 1 && s == WU) dst = &g_SfA[c][r];
                else if ((c == 0 && s == 63) || (c >= 1 && c <= CCH - 2 && s == WU + 64)) dst = &g_SoA[c][r];
                else if (c == CCH - 1 && s == WU + 63) dst = &g_SlA[r];
            } else {
                if (c <= CCH - 2 && s == WU) dst = &g_SfB[c][r];
                else if ((c == CCH - 1 && s == 63) || (c >= 1 && c <= CCH - 2 && s == WU + 64)) dst = &g_SoB[c][r];
            }
            if (dst) {
                float l8 = (mode == 0)
                    ? (pA.x + pA.y + pA.z + pA.w + pB.x + pB.y + pB.z + pB.w)
                    : (aA.x + aA.y + aA.z + aA.w + aB.x + aB.y + aB.z + aB.w);
                if (lane == 0) s_redf[w] = l8;
                __syncthreads();
                if (tid == 0) {
                    float ss = 0.f;
                    for (int i = 0; i < 16; ++i) ss += s_redf[i];
                    *dst = ss;
                }
            }
        } else {
            // ---- exact Viterbi step (bit-identical semantics) ----
            unsigned int bu[8]; int bi[8];
#pragma unroll
            for (int j = 0; j < 8; ++j) { bu[j] = 0u; bi[j] = lane; }
#pragma unroll
            for (int kk = 0; kk < 8; ++kk) {
                int k = kk * 32 + lane;
                float vv = vreg[kk];
                unsigned int sc[8];
                sc[0] = __float_as_uint(fmul_ftz(vv, aqA[kk].x));
                sc[1] = __float_as_uint(fmul_ftz(vv, aqA[kk].y));
                sc[2] = __float_as_uint(fmul_ftz(vv, aqA[kk].z));
                sc[3] = __float_as_uint(fmul_ftz(vv, aqA[kk].w));
                sc[4] = __float_as_uint(fmul_ftz(vv, aqB[kk].x));
                sc[5] = __float_as_uint(fmul_ftz(vv, aqB[kk].y));
                sc[6] = __float_as_uint(fmul_ftz(vv, aqB[kk].z));
                sc[7] = __float_as_uint(fmul_ftz(vv, aqB[kk].w));
#pragma unroll
                for (int j = 0; j < 8; ++j)
                    if (sc[j] > bu[j]) { bu[j] = sc[j]; bi[j] = k; }
            }
#pragma unroll
            for (int off = 16; off > 0; off >>= 1) {
#pragma unroll
                for (int j = 0; j < 8; ++j) {
                    unsigned int ou = __shfl_xor_sync(0xffffffffu, bu[j], off);
                    int oi = __shfl_xor_sync(0xffffffffu, bi[j], off);
                    if (ou > bu[j] || (ou == bu[j] && oi < bi[j])) { bu[j] = ou; bi[j] = oi; }
                }
            }
            float4 pA, pB;
            pA.x = fmul_ftz(bxA.x, __uint_as_float(bu[0]));
            pA.y = fmul_ftz(bxA.y, __uint_as_float(bu[1]));
            pA.z = fmul_ftz(bxA.z, __uint_as_float(bu[2]));
            pA.w = fmul_ftz(bxA.w, __uint_as_float(bu[3]));
            pB.x = fmul_ftz(bxB.x, __uint_as_float(bu[4]));
            pB.y = fmul_ftz(bxB.y, __uint_as_float(bu[5]));
            pB.z = fmul_ftz(bxB.z, __uint_as_float(bu[6]));
            pB.w = fmul_ftz(bxB.w, __uint_as_float(bu[7]));
            if (lane == 0) {
                push_quad(nbuf, r ^ 1u, pA);
                push_quad(nbuf + 16u, r ^ 1u, pB);
                flag_release(flagu + (unsigned int)(slot2 * 32 + 16 + w) * 4u, r ^ 1u, tag);
            } else if (lane == 1) {
                push_quad(nbuf, r, pA);
                push_quad(nbuf + 16u, r, pB);
                flag_release(flagu + (unsigned int)(slot2 * 32 + w) * 4u, r, tag);
            } else if (lane == 3) {
                uint2 pk;
                pk.x = (unsigned int)bi[0] | ((unsigned int)bi[1] << 8)
                     | ((unsigned int)bi[2] << 16) | ((unsigned int)bi[3] << 24);
                pk.y = (unsigned int)bi[4] | ((unsigned int)bi[5] << 8)
                     | ((unsigned int)bi[6] << 16) | ((unsigned int)bi[7] << 24);
                *(uint2*)(g_bp + (size_t)(t - 1) * YS + cbase) = pk;
                // mirror early rows into rank 0's SMEM for the fast backtrack
                if (t - 1 < 64) {
                    unsigned long long v64 =
                        (unsigned long long)pk.x | ((unsigned long long)pk.y << 32);
                    push_u64(bpcu + (unsigned int)((t - 1) * YS + cbase), 0u, v64);
                }
            }
        }

        if (s + 1 < nsteps) {
            int tn = (mode == 1) ? (tbase - (s + 1)) : (tbase + (s + 1));
            bxA = __ldg((const float4*)&g_bx[tn * YS + cbase]);
            bxB = __ldg((const float4*)&g_bx[tn * YS + cbase + 4]);
        }
    }

    // ---- epilogues ----
    if (mode == 0) {
        if (c == CCH - 1 && r == 0) {
            // nothing extra: p computed in stitch from g_SlA
        }
    } else if (mode == 2) {
        if (tz >= 0) {
            unsigned int* bp32 = (unsigned int*)(g_bp + (size_t)tz * YS);
            int n32 = (TM1 - tz) * (YS / 4);
            for (int i = (int)r * 512 + tid; i < n32; i += 1024) bp32[i] = 0u;
        }
        CLUSTER_ARRIVE();   // orders remote s_bpc stores + zero-fill before backtrack
        CLUSTER_WAIT();
        if (r == 0) {
            if (tz >= 0) {
                for (int k = tz + tid; k < TS - 1; k += 512)
                    out[OFF_PATH + k] = 0.0f;
            } else if (w == 0) {
                const int fslot = TM1 % NSLOT;
                const unsigned int fa = flagu + (unsigned int)(fslot * 32 + lane) * 4u;
                bool ok;
                do { ok = (ld_rlx(fa) >= (unsigned int)TM1); }
                while (!__all_sync(0xffffffffu, ok));
                ld_acq(fa);
                if (lane == 0) {
                    unsigned int m = __float_as_uint(s_buf[fslot][0]);
                    int idx = 0;
                    for (int i = 1; i < YS; ++i) {
                        unsigned int vi = __float_as_uint(s_buf[fslot][i]);
                        if (vi > m) { m = vi; idx = i; }
                    }
                    s_last = idx;
                }
            }
            __syncthreads();
            if (tid == 0) {
                int last = s_last;
                out[OFF_PATH + TS - 1] = (float)last;
                int st = last;
                int tstart = (tz >= 0) ? (tz - 1) : (TS - 2);
                for (int tt = tstart; tt >= 0; --tt) {
                    st = (tt < 64) ? (int)s_bpc[tt * YS + st]
                                   : (int)g_bp[(size_t)tt * YS + st];
                    out[OFF_PATH + tt] = (float)st;
                }
            }
        }
    }

    CLUSTER_ARRIVE();
    CLUSTER_WAIT();
}

// ---------------------------------------------------------------- stitch
__global__ void stitch_kernel(float* __restrict__ out) {
    __shared__ float sSoA[CCH], sSfA[CCH], sSoB[CCH], sSfB[CCH];
    int tid = threadIdx.x;  // 64 threads
    if (tid < CCH) {
        sSoA[tid] = g_SoA[tid][0] + g_SoA[tid][1];
        sSfA[tid] = g_SfA[tid][0] + g_SfA[tid][1];
    } else {
        int c = tid - CCH;
        sSoB[c] = g_SoB[c][0] + g_SoB[c][1];
        sSfB[c] = g_SfB[c][0] + g_SfB[c][1];
    }
    __syncthreads();
    if (tid == 0) {
        double k = 1.0;
        g_kap[0] = 1.0f;
        for (int c = 1; c < CCH; ++c) {
            k *= (double)sSoA[c - 1] / (double)sSfA[c];
            g_kap[c] = (float)k;
        }
        double p = k * (double)(g_SlA[0] + g_SlA[1]);
        g_p = (float)p;
        out[OFF_P] = (float)p;
    }
    if (tid == 32) {
        double l = 1.0;
        g_lam[CCH - 1] = 1.0f;
        for (int c = CCH - 2; c >= 0; --c) {
            l *= (double)sSoB[c + 1] / (double)sSfB[c];
            g_lam[c] = (float)l;
        }
    }
}

// ---------------------------------------------------------------- xi (fused)
// block t in [0,2046]: applies kappa/lambda scales in registers, writes final
// alpha[t], beta[t+1], gamma[t], and xi[t]. Raw values come from g_alpha/g_beta.
#define XG 8
__global__ void xi_fused_kernel(const float* __restrict__ A, float* __restrict__ out) {
    __shared__ __align__(16) float s_a[YS];
    __shared__ __align__(16) float s_w[YS];
    __shared__ __align__(16) float s_x[XG][264];
    int t = blockIdx.x, tid = threadIdx.x;
    float ka  = g_kap[t >> 6];
    float la0 = g_lam[t >> 6];
    float la1 = g_lam[(t + 1) >> 6];

    float av = g_alpha[t * YS + tid] * ka;                 // scaled alpha[t]
    float b1 = g_beta[(t + 1) * YS + tid] * la1;           // scaled beta[t+1]
    float b0 = g_beta[t * YS + tid] * la0;                 // scaled beta[t]
    s_a[tid] = av;
    s_w[tid] = g_bx[(t + 1) * YS + tid] * b1;
    out[OFF_ALPHA + t * YS + tid] = av;
    out[OFF_BETA + (t + 1) * YS + tid] = b1;
    out[OFF_GAMMA + t * YS + tid] = av * b0 / g_p;
    __syncthreads();

    float wj = s_w[tid];
    const float* Ac = A + tid;
    float* base = out + OFF_XI + (size_t)t * YS * YS;

    for (int g0 = 0; g0 < YS; g0 += XG) {
#pragma unroll
        for (int q = 0; q < XG; ++q) {
            int i = g0 + q;
            float a2 = __ldg(Ac + (size_t)i * YS);
            s_x[q][tid + 1] = (s_a[i] * a2) * wj;
        }
        __syncthreads();
#pragma unroll 2
        for (int u = tid; u < XG * 63; u += YS) {
            int row = u / 63, q = u - row * 63;
            float4 v = *(const float4*)&s_x[row][4 + 4 * q];
            *(float4*)(base + (size_t)(g0 + row) * YS + 3 + 4 * q) = v;
        }
        if (tid < XG * 4) {
            int row = tid >> 2, cc = tid & 3;
            int col = (cc < 3) ? cc : 255;
            base[(size_t)(g0 + row) * YS + col] = s_x[row][col + 1];
        }
        __syncthreads();
    }
}

// ---------------------------------------------------------------- tail
// Rows not covered by xi_fused: alpha[2047], beta[0], gamma[2047].
__global__ void tail_kernel(float* __restrict__ out) {
    int tid = threadIdx.x;
    float a  = g_alpha[(TS - 1) * YS + tid] * g_kap[CCH - 1];
    float bT = g_beta[(TS - 1) * YS + tid] * g_lam[CCH - 1];
    out[OFF_ALPHA + (TS - 1) * YS + tid] = a;
    out[OFF_BETA + tid] = g_beta[tid] * g_lam[0];
    out[OFF_GAMMA + (TS - 1) * YS + tid] = a * bT / g_p;
}

// ---------------------------------------------------------------- launch
extern "C" void kernel_launch(void* const* d_in, const int* in_sizes, int n_in,
                              void* d_out, int out_size) {
    const int*   x  = (const int*)d_in[0];
    const float* A  = (const float*)d_in[1];
    const float* b  = (const float*)d_in[2];
    const float* pi = (const float*)d_in[3];
    float* out = (float*)d_out;

    prep_bx_kernel<<<TS, YS>>>(x, b);
    dummy_kernel<<<1, 32>>>();
    dummy_kernel<<<1, 32>>>();
    chunk_kernel<<<2 * (1 + 2 * CCH), 512>>>(A, pi, out);   // 4th launch -> ncu
    stitch_kernel<<<1, 64>>>(out);
    xi_fused_kernel<<<TM1, YS>>>(A, out);
    tail_kernel<<<1, YS>>>(out);
}